// round 10
// baseline (speedup 1.0000x reference)
#include <cuda_runtime.h>
#include <cuda_bf16.h>

// Shapes
#define BHTOK 1024   // B*H
#define NKEY  128
#define CDIM  256
#define C8    32
#define HIDF  1024

typedef unsigned long long ULL;

// ---------------- device scratch (no allocations allowed) ----------------
__device__ float g_Wks[CDIM*C8];    // Wk @ sc_w1
__device__ float g_Wqs[CDIM*C8];    // Wq @ sc_w1
__device__ float g_Pws[C8*C8];      // pos_w2 @ sc_w1
__device__ float g_cb [C8];         // pos_b2 @ sc_w1 + sc_b1
__device__ float g_agg[BHTOK*CDIM];
__device__ float g_x  [BHTOK*CDIM]; // attn_out + query  (residual stream)
__device__ float g_xln[BHTOK*CDIM]; // LN2(g_x)
__device__ float g_hh [BHTOK*HIDF]; // relu(ff1)

// ---------------- helpers ----------------
__device__ __forceinline__ ULL pk2(float lo, float hi) {
    ULL r; asm("mov.b64 %0, {%1,%2};" : "=l"(r) : "f"(lo), "f"(hi)); return r;
}
__device__ __forceinline__ void upk2(ULL v, float& lo, float& hi) {
    asm("mov.b64 {%0,%1}, %2;" : "=f"(lo), "=f"(hi) : "l"(v));
}
__device__ __forceinline__ void ffma2(ULL& d, ULL a, ULL b) {
    asm("fma.rn.f32x2 %0, %1, %2, %0;" : "+l"(d) : "l"(a), "l"(b));
}

// block = 256 threads (8 warps), sred >= 8 floats
__device__ __forceinline__ float brsum(float v, float* sred) {
    #pragma unroll
    for (int o = 16; o > 0; o >>= 1) v += __shfl_down_sync(0xffffffffu, v, o);
    __syncthreads();
    if ((threadIdx.x & 31) == 0) sred[threadIdx.x >> 5] = v;
    __syncthreads();
    float s = 0.f;
    #pragma unroll
    for (int i = 0; i < 8; i++) s += sred[i];
    return s;
}

// ---------------- kFold: fold weights through sc_w1 ----------------
__global__ __launch_bounds__(256) void kFold(
    const float* __restrict__ Wq, const float* __restrict__ Wk,
    const float* __restrict__ sc_w1, const float* __restrict__ sc_b1,
    const float* __restrict__ pos_w2, const float* __restrict__ pos_b2)
{
    int b = blockIdx.x, t = threadIdx.x;
    if (b < 64) {
        const float* W = (b < 32) ? Wk : Wq;
        float* dst     = (b < 32) ? g_Wks : g_Wqs;
        int o = (b & 31) * 256 + t;     // o = d*32 + j
        int d = o >> 5, j = o & 31;
        float a = 0.f;
        #pragma unroll 4
        for (int c = 0; c < 256; c++) a += W[d*256 + c] * sc_w1[c*32 + j];
        dst[o] = a;
    } else {
        #pragma unroll
        for (int k = 0; k < 4; k++) {
            int o = t + (k << 8);       // o = tt*32 + j
            int tt = o >> 5, j = o & 31;
            float a = 0.f;
            #pragma unroll 4
            for (int c = 0; c < 256; c++) a += pos_w2[tt*256 + c] * sc_w1[c*32 + j];
            g_Pws[o] = a;
        }
        if (t < 32) {
            float a = sc_b1[t];
            #pragma unroll 4
            for (int c = 0; c < 256; c++) a += pos_b2[c] * sc_w1[c*32 + t];
            g_cb[t] = a;
        }
    }
}

// ---------------- kAttn: fused attention per token ----------------
// Shared layout (float indices):
//   [0, 32768)        s_key   [128][256] fp32
//   [32768, 49152)    region R: first s_wks (8192 f), then s_w bf16[128][256]
//   [49152, 53248)    s_h1    [128][32]
//   [53248, 57344)    s_s1    [128][32]
//   [57344, 57600)    s_xln   [256]
//   [57600, 57632)    s_qs    [32]
//   [57632, 57760)    s_vis   [128] (int)
//   [57760, 57792)    s_red   [32]
#define SMEM_FLOATS 57792
#define SMEM_BYTES  (SMEM_FLOATS * 4)   // 231168 B

__global__ __launch_bounds__(256, 1) void kAttn(
    const float* __restrict__ query, const float* __restrict__ key,
    const float* __restrict__ rel,   const int*   __restrict__ vis,
    const float* __restrict__ ln1_g, const float* __restrict__ ln1_b,
    const float* __restrict__ pos_w1,const float* __restrict__ pos_b1,
    const float* __restrict__ sc_w2, const float* __restrict__ sc_b2,
    const float* __restrict__ pos_w2,const float* __restrict__ pos_b2,
    const float* __restrict__ Wv)
{
    extern __shared__ float sm[];
    float*          s_key = sm;
    float*          s_wks = sm + 32768;
    __nv_bfloat16*  s_w   = (__nv_bfloat16*)(sm + 32768);
    float*          s_h1  = sm + 49152;
    float*          s_s1  = sm + 53248;
    float*          s_xln = sm + 57344;
    float*          s_qs  = sm + 57600;
    int*            s_vis = (int*)(sm + 57632);
    float*          s_red = sm + 57760;

    const int bh   = blockIdx.x;
    const int tid  = threadIdx.x;
    const int lane = tid & 31;
    const int wid  = tid >> 5;

    // ---- phase 0: LN1 on the query row ----
    float qv = query[bh*256 + tid];
    float m  = brsum(qv, s_red) * (1.f/256.f);
    float dv = qv - m;
    float var = brsum(dv*dv, s_red) * (1.f/256.f);
    float rstd = rsqrtf(var + 1e-6f);
    s_xln[tid] = dv * rstd * ln1_g[tid] + ln1_b[tid];
    __syncthreads();

    // ---- phase 1: stage key tile, Wks, vis; compute h1; warp0 computes qs ----
    {
        const float4* ksrc = (const float4*)(key + (size_t)bh * (NKEY*CDIM));
        float4* kdst = (float4*)s_key;
        #pragma unroll
        for (int i = 0; i < 32; i++) kdst[tid + i*256] = ksrc[tid + i*256];

        const float4* wsrc = (const float4*)g_Wks;
        float4* wdst = (float4*)s_wks;
        #pragma unroll
        for (int i = 0; i < 8; i++) wdst[tid + i*256] = wsrc[tid + i*256];

        if (tid < 128) s_vis[tid] = vis[bh*128 + tid];

        // h1[n,t] = relu(rel[n,:4] @ pos_w1[:,t] + pos_b1[t])
        #pragma unroll
        for (int i = 0; i < 16; i++) {
            int o = tid + i*256;            // o = n*32 + t
            int n = o >> 5, t = o & 31;
            const float* rp = rel + (size_t)(bh*128 + n)*4;
            float a = pos_b1[t];
            a += rp[0]*pos_w1[0*32 + t];
            a += rp[1]*pos_w1[1*32 + t];
            a += rp[2]*pos_w1[2*32 + t];
            a += rp[3]*pos_w1[3*32 + t];
            s_h1[o] = fmaxf(a, 0.f);
        }

        if (wid == 0) { // qs[j] = xln @ Wqs[:,j]
            float a = 0.f;
            #pragma unroll 4
            for (int c = 0; c < 256; c++) a += s_xln[c] * g_Wqs[c*32 + lane];
            s_qs[lane] = a;
        }
    }
    __syncthreads();

    // ---- phase 2: s1[n,j] = relu(key@Wks + h1@Pws + cb - qs) ----
    {
        const int j = lane;
        const float cbmq = g_cb[j] - s_qs[j];
        #pragma unroll 2
        for (int i = 0; i < 16; i++) {
            int n = wid*16 + i;
            float acc = cbmq;
            const float* h1r = s_h1 + n*32;
            #pragma unroll
            for (int t = 0; t < 32; t += 4) {
                float4 h4 = *(const float4*)(h1r + t);
                acc += h4.x*g_Pws[(t+0)*32 + j];
                acc += h4.y*g_Pws[(t+1)*32 + j];
                acc += h4.z*g_Pws[(t+2)*32 + j];
                acc += h4.w*g_Pws[(t+3)*32 + j];
            }
            const float* kr = s_key + n*256;
            #pragma unroll 4
            for (int c = 0; c < 256; c += 4) {
                float4 k4 = *(const float4*)(kr + c);
                acc += k4.x*s_wks[(c+0)*32 + j];
                acc += k4.y*s_wks[(c+1)*32 + j];
                acc += k4.z*s_wks[(c+2)*32 + j];
                acc += k4.w*s_wks[(c+3)*32 + j];
            }
            s_s1[n*32 + j] = fmaxf(acc, 0.f);
        }
    }
    __syncthreads();   // s_wks dead after this; region becomes s_w (bf16)

    // ---- phase 3: logits (thread <-> channel c = tid), masked, stored bf16 ----
    const int c = tid;
    {
        float w2r[32];
        #pragma unroll
        for (int j = 0; j < 32; j++) w2r[j] = sc_w2[j*256 + c];
        const float sb2 = sc_b2[c];
        for (int n = 0; n < 128; n++) {
            const float* s1r = s_s1 + n*32;
            float acc = sb2;
            #pragma unroll
            for (int j = 0; j < 32; j++) acc += s1r[j] * w2r[j];
            float l = (s_vis[n] == 0) ? -1e9f : acc;
            s_w[n*256 + c] = __float2bfloat16(l);
        }
    }

    // ---- phase 4: per-channel softmax stats; overwrite s_w with exp(l-m) ----
    float inv;
    {
        float mx = -3e38f;
        #pragma unroll 4
        for (int n = 0; n < 128; n++) {
            float l = __bfloat162float(s_w[n*256 + c]);
            mx = fmaxf(mx, l);
        }
        float s = 0.f;
        #pragma unroll 4
        for (int n = 0; n < 128; n++) {
            float l = __bfloat162float(s_w[n*256 + c]);
            float e = __expf(l - mx);
            __nv_bfloat16 eb = __float2bfloat16(e);
            s_w[n*256 + c] = eb;
            s += __bfloat162float(eb);     // sum exactly what phase 5 reads
        }
        inv = 1.f / s;
    }
    // no sync needed: columns are thread-private from here on

    // ---- phase 5: agg[c] = inv*( sum_d Wv[d,c]*G_d + sum_t pos_w2[t,c]*P_t ) + pos_b2[c]
    float aggv = 0.f;
    {
        const float* wvp = Wv + c;
        for (int d0 = 0; d0 < 256; d0 += 16) {
            ULL g0=0,g1=0,g2=0,g3=0,g4=0,g5=0,g6=0,g7=0;
            const char* kbase = (const char*)(s_key + d0);
            #pragma unroll 4
            for (int n = 0; n < 128; n++) {
                float w = __bfloat162float(s_w[n*256 + c]);
                ULL w2 = pk2(w, w);
                const ulonglong2* kp = (const ulonglong2*)(kbase + n*1024);
                ulonglong2 a = kp[0], b = kp[1], e = kp[2], f = kp[3];
                ffma2(g0, w2, a.x); ffma2(g1, w2, a.y);
                ffma2(g2, w2, b.x); ffma2(g3, w2, b.y);
                ffma2(g4, w2, e.x); ffma2(g5, w2, e.y);
                ffma2(g6, w2, f.x); ffma2(g7, w2, f.y);
            }
            float lo, hi;
            upk2(g0, lo, hi); aggv += lo*wvp[(d0+ 0)*256] + hi*wvp[(d0+ 1)*256];
            upk2(g1, lo, hi); aggv += lo*wvp[(d0+ 2)*256] + hi*wvp[(d0+ 3)*256];
            upk2(g2, lo, hi); aggv += lo*wvp[(d0+ 4)*256] + hi*wvp[(d0+ 5)*256];
            upk2(g3, lo, hi); aggv += lo*wvp[(d0+ 6)*256] + hi*wvp[(d0+ 7)*256];
            upk2(g4, lo, hi); aggv += lo*wvp[(d0+ 8)*256] + hi*wvp[(d0+ 9)*256];
            upk2(g5, lo, hi); aggv += lo*wvp[(d0+10)*256] + hi*wvp[(d0+11)*256];
            upk2(g6, lo, hi); aggv += lo*wvp[(d0+12)*256] + hi*wvp[(d0+13)*256];
            upk2(g7, lo, hi); aggv += lo*wvp[(d0+14)*256] + hi*wvp[(d0+15)*256];
        }
        // pos contribution
        for (int t0 = 0; t0 < 32; t0 += 8) {
            float p0=0,p1=0,p2=0,p3=0,p4=0,p5=0,p6=0,p7=0;
            #pragma unroll 4
            for (int n = 0; n < 128; n++) {
                float w = __bfloat162float(s_w[n*256 + c]);
                const float4* hp = (const float4*)(s_h1 + n*32 + t0);
                float4 ha = hp[0], hb = hp[1];
                p0 += w*ha.x; p1 += w*ha.y; p2 += w*ha.z; p3 += w*ha.w;
                p4 += w*hb.x; p5 += w*hb.y; p6 += w*hb.z; p7 += w*hb.w;
            }
            aggv += p0*pos_w2[(t0+0)*256 + c] + p1*pos_w2[(t0+1)*256 + c]
                  + p2*pos_w2[(t0+2)*256 + c] + p3*pos_w2[(t0+3)*256 + c]
                  + p4*pos_w2[(t0+4)*256 + c] + p5*pos_w2[(t0+5)*256 + c]
                  + p6*pos_w2[(t0+6)*256 + c] + p7*pos_w2[(t0+7)*256 + c];
        }
    }
    g_agg[bh*256 + c] = inv * aggv + pos_b2[c];
}

// ---------------- kOut: agg@Wo + bo + query residual, then LN2 ----------------
__global__ __launch_bounds__(256) void kOut(
    const float* __restrict__ query, const float* __restrict__ Wo,
    const float* __restrict__ bo,
    const float* __restrict__ ln2_g, const float* __restrict__ ln2_b)
{
    __shared__ float s_a[256];
    __shared__ float s_red[8];
    const int bh = blockIdx.x, c = threadIdx.x;
    s_a[c] = g_agg[bh*256 + c];
    __syncthreads();
    float acc = bo[c];
    #pragma unroll 4
    for (int d = 0; d < 256; d += 4) {
        float4 a4 = *(const float4*)(s_a + d);
        acc += a4.x*Wo[(d+0)*256 + c];
        acc += a4.y*Wo[(d+1)*256 + c];
        acc += a4.z*Wo[(d+2)*256 + c];
        acc += a4.w*Wo[(d+3)*256 + c];
    }
    float x2 = acc + query[bh*256 + c];
    g_x[bh*256 + c] = x2;
    float m = brsum(x2, s_red) * (1.f/256.f);
    float dv = x2 - m;
    float var = brsum(dv*dv, s_red) * (1.f/256.f);
    float rstd = rsqrtf(var + 1e-6f);
    g_xln[bh*256 + c] = dv * rstd * ln2_g[c] + ln2_b[c];
}

// ---------------- kFF1: h = relu(xln2 @ ff_w1 + ff_b1) ----------------
__global__ __launch_bounds__(256) void kFF1(
    const float* __restrict__ ff_w1, const float* __restrict__ ff_b1)
{
    __shared__ float s_x[256];
    const int bh = blockIdx.x, tid = threadIdx.x;
    s_x[tid] = g_xln[bh*256 + tid];
    __syncthreads();
    const int c0 = tid * 4;
    float4 acc = *(const float4*)(ff_b1 + c0);
    #pragma unroll 4
    for (int d = 0; d < 256; d++) {
        float xv = s_x[d];
        float4 w4 = *(const float4*)(ff_w1 + d*1024 + c0);
        acc.x += xv*w4.x; acc.y += xv*w4.y; acc.z += xv*w4.z; acc.w += xv*w4.w;
    }
    acc.x = fmaxf(acc.x, 0.f); acc.y = fmaxf(acc.y, 0.f);
    acc.z = fmaxf(acc.z, 0.f); acc.w = fmaxf(acc.w, 0.f);
    *(float4*)(g_hh + (size_t)bh*1024 + c0) = acc;
}

// ---------------- kFF2: out = h @ ff_w2 + ff_b2 + x2 ----------------
__global__ __launch_bounds__(256) void kFF2(
    const float* __restrict__ ff_w2, const float* __restrict__ ff_b2,
    float* __restrict__ out)
{
    __shared__ float s_h[4*1024];
    const int blk = blockIdx.x, tid = threadIdx.x;
    const float4* src = (const float4*)(g_hh + (size_t)blk*4096);
    float4* dst = (float4*)s_h;
    #pragma unroll
    for (int i = 0; i < 4; i++) dst[tid + i*256] = src[tid + i*256];
    __syncthreads();
    const int lr = tid >> 6;             // local row 0..3
    const int r  = blk*4 + lr;           // token
    const int c0 = (tid & 63) * 4;       // 4 consecutive channels
    float4 acc = *(const float4*)(ff_b2 + c0);
    const float* hr = s_h + lr*1024;
    #pragma unroll 4
    for (int d = 0; d < 1024; d++) {
        float hv = hr[d];
        float4 w4 = *(const float4*)(ff_w2 + d*256 + c0);
        acc.x += hv*w4.x; acc.y += hv*w4.y; acc.z += hv*w4.z; acc.w += hv*w4.w;
    }
    float4 xr = *(const float4*)(g_x + r*256 + c0);
    acc.x += xr.x; acc.y += xr.y; acc.z += xr.z; acc.w += xr.w;
    *(float4*)(out + r*256 + c0) = acc;
}

// ---------------- launch ----------------
extern "C" void kernel_launch(void* const* d_in, const int* in_sizes, int n_in,
                              void* d_out, int out_size) {
    (void)in_sizes; (void)n_in; (void)out_size;
    const float* query  = (const float*)d_in[0];
    const float* key    = (const float*)d_in[1];
    const float* rel    = (const float*)d_in[2];
    const int*   vis    = (const int*)  d_in[3];
    const float* ln1_g  = (const float*)d_in[4];
    const float* ln1_b  = (const float*)d_in[5];
    const float* ln2_g  = (const float*)d_in[6];
    const float* ln2_b  = (const float*)d_in[7];
    const float* Wq     = (const float*)d_in[8];
    const float* Wk     = (const float*)d_in[9];
    const float* Wv     = (const float*)d_in[10];
    const float* pos_w1 = (const float*)d_in[11];
    const float* pos_b1 = (const float*)d_in[12];
    const float* pos_w2 = (const float*)d_in[13];
    const float* pos_b2 = (const float*)d_in[14];
    const float* sc_w1  = (const float*)d_in[15];
    const float* sc_b1  = (const float*)d_in[16];
    const float* sc_w2  = (const float*)d_in[17];
    const float* sc_b2  = (const float*)d_in[18];
    const float* Wo     = (const float*)d_in[19];
    const float* bo     = (const float*)d_in[20];
    const float* ff_w1  = (const float*)d_in[21];
    const float* ff_b1  = (const float*)d_in[22];
    const float* ff_w2  = (const float*)d_in[23];
    const float* ff_b2  = (const float*)d_in[24];
    float* out = (float*)d_out;

    cudaFuncSetAttribute(kAttn, cudaFuncAttributeMaxDynamicSharedMemorySize, SMEM_BYTES);

    kFold<<<65, 256>>>(Wq, Wk, sc_w1, sc_b1, pos_w2, pos_b2);
    kAttn<<<BHTOK, 256, SMEM_BYTES>>>(query, key, rel, vis, ln1_g, ln1_b,
                                      pos_w1, pos_b1, sc_w2, sc_b2,
                                      pos_w2, pos_b2, Wv);
    kOut<<<BHTOK, 256>>>(query, Wo, bo, ln2_g, ln2_b);
    kFF1<<<BHTOK, 256>>>(ff_w1, ff_b1);
    kFF2<<<BHTOK/4, 256>>>(ff_w2, ff_b2, out);
}

// round 11
// speedup vs baseline: 1.6430x; 1.6430x over previous
#include <cuda_runtime.h>
#include <cuda_bf16.h>
#include <stdint.h>

// Shapes
#define BHTOK 1024   // B*H
#define NKEY  128
#define CDIM  256
#define C8    32
#define HIDF  1024
#define MTOT  (BHTOK*NKEY)   // 131072
#define KDIM  288            // 256 key + 32 h1
#define NDIM  288            // 256 v' + 32 s1pre'

// ---------------- device scratch (no allocations allowed) ----------------
__device__ float g_Wks[CDIM*C8];    // Wk @ sc_w1
__device__ float g_Wqs[CDIM*C8];    // Wq @ sc_w1
__device__ float g_Pws[C8*C8];      // pos_w2 @ sc_w1
__device__ float g_cb [C8];         // pos_b2 @ sc_w1 + sc_b1
__device__ __nv_bfloat16 g_ab[(size_t)MTOT*KDIM];   // A = [key | h1]  (75.5 MB)
__device__ __nv_bfloat16 g_Bm[KDIM*NDIM];           // B = [[Wv|Wks],[pos_w2|Pws]]
__device__ __nv_bfloat16 g_v [(size_t)MTOT*CDIM];   // v + pos - pos_b2 (67 MB)
__device__ float g_s1p[(size_t)MTOT*C8];            // s1 pre-activation (partial)
__device__ float g_agg[BHTOK*CDIM];
__device__ float g_x  [BHTOK*CDIM];
__device__ float g_xln[BHTOK*CDIM];
__device__ float g_hh [BHTOK*HIDF];

// ---------------- helpers ----------------
__device__ __forceinline__ float brsum(float v, float* sred) {
    #pragma unroll
    for (int o = 16; o > 0; o >>= 1) v += __shfl_down_sync(0xffffffffu, v, o);
    __syncthreads();
    if ((threadIdx.x & 31) == 0) sred[threadIdx.x >> 5] = v;
    __syncthreads();
    float s = 0.f;
    #pragma unroll
    for (int i = 0; i < 8; i++) s += sred[i];
    return s;
}

__device__ __forceinline__ void ldsm4(uint32_t* r, uint32_t addr) {
    asm volatile("ldmatrix.sync.aligned.m8n8.x4.shared.b16 {%0,%1,%2,%3}, [%4];"
        : "=r"(r[0]), "=r"(r[1]), "=r"(r[2]), "=r"(r[3]) : "r"(addr));
}
__device__ __forceinline__ void ldsm4t(uint32_t* r, uint32_t addr) {
    asm volatile("ldmatrix.sync.aligned.m8n8.x4.trans.shared.b16 {%0,%1,%2,%3}, [%4];"
        : "=r"(r[0]), "=r"(r[1]), "=r"(r[2]), "=r"(r[3]) : "r"(addr));
}
__device__ __forceinline__ void mma16816(float* c, const uint32_t* a,
                                         uint32_t b0, uint32_t b1) {
    asm volatile("mma.sync.aligned.m16n8k16.row.col.f32.bf16.bf16.f32 "
        "{%0,%1,%2,%3}, {%4,%5,%6,%7}, {%8,%9}, {%0,%1,%2,%3};"
        : "+f"(c[0]), "+f"(c[1]), "+f"(c[2]), "+f"(c[3])
        : "r"(a[0]), "r"(a[1]), "r"(a[2]), "r"(a[3]), "r"(b0), "r"(b1));
}

// ---------------- kFold: fold weights through sc_w1 ----------------
__global__ __launch_bounds__(256) void kFold(
    const float* __restrict__ Wq, const float* __restrict__ Wk,
    const float* __restrict__ sc_w1, const float* __restrict__ sc_b1,
    const float* __restrict__ pos_w2, const float* __restrict__ pos_b2)
{
    int b = blockIdx.x, t = threadIdx.x;
    if (b < 64) {
        const float* W = (b < 32) ? Wk : Wq;
        float* dst     = (b < 32) ? g_Wks : g_Wqs;
        int o = (b & 31) * 256 + t;     // o = d*32 + j
        int d = o >> 5, j = o & 31;
        float a = 0.f;
        #pragma unroll 4
        for (int c = 0; c < 256; c++) a += W[d*256 + c] * sc_w1[c*32 + j];
        dst[o] = a;
    } else {
        #pragma unroll
        for (int k = 0; k < 4; k++) {
            int o = t + (k << 8);       // o = tt*32 + j
            int tt = o >> 5, j = o & 31;
            float a = 0.f;
            #pragma unroll 4
            for (int c = 0; c < 256; c++) a += pos_w2[tt*256 + c] * sc_w1[c*32 + j];
            g_Pws[o] = a;
        }
        if (t < 32) {
            float a = sc_b1[t];
            #pragma unroll 4
            for (int c = 0; c < 256; c++) a += pos_b2[c] * sc_w1[c*32 + t];
            g_cb[t] = a;
        }
    }
}

// ---------------- kPrep: build bf16 A=[key|h1] and B matrices ----------------
__global__ __launch_bounds__(256) void kPrep(
    const float* __restrict__ key, const float* __restrict__ rel,
    const float* __restrict__ pos_w1, const float* __restrict__ pos_b1,
    const float* __restrict__ Wv, const float* __restrict__ pos_w2)
{
    int b = blockIdx.x, t = threadIdx.x;
    if (b < BHTOK) {
        // key -> bf16 into cols [0,256)
        const float4* src = (const float4*)(key + (size_t)b * 32768);
        #pragma unroll
        for (int i = 0; i < 32; i++) {
            int idx = t + i * 256;              // float4 index 0..8191
            int row = idx >> 6, q = idx & 63;   // row 0..127, q 0..63
            float4 v4 = src[idx];
            __nv_bfloat162* dst = (__nv_bfloat162*)(g_ab + ((size_t)(b*128 + row))*KDIM + q*4);
            dst[0] = __floats2bfloat162_rn(v4.x, v4.y);
            dst[1] = __floats2bfloat162_rn(v4.z, v4.w);
        }
        // h1 = relu(rel @ pos_w1 + pos_b1) -> bf16 into cols [256,288)
        #pragma unroll
        for (int i = 0; i < 16; i++) {
            int o = t + i * 256;                // o = n*32 + tt
            int n = o >> 5, tt = o & 31;
            const float* rp = rel + (size_t)(b*128 + n) * 4;
            float a = pos_b1[tt];
            a += rp[0]*pos_w1[0*32 + tt];
            a += rp[1]*pos_w1[1*32 + tt];
            a += rp[2]*pos_w1[2*32 + tt];
            a += rp[3]*pos_w1[3*32 + tt];
            g_ab[((size_t)(b*128 + n))*KDIM + 256 + tt] = __float2bfloat16(fmaxf(a, 0.f));
        }
    } else {
        // B matrix [288 x 288]
        for (int idx = t; idx < KDIM*NDIM; idx += 256) {
            int r = idx / NDIM, c = idx % NDIM;
            float v;
            if (r < 256) v = (c < 256) ? Wv[r*256 + c]          : g_Wks[r*32 + (c-256)];
            else         v = (c < 256) ? pos_w2[(r-256)*256 + c] : g_Pws[(r-256)*32 + (c-256)];
            g_Bm[idx] = __float2bfloat16(v);
        }
    }
}

// ---------------- kGemm: C[131072,288] = A[131072,288] @ B[288,288] ----------------
// BM=128, BN=96, BK=32. mma.sync m16n8k16 bf16. Warps 4(M) x 2(N), warp tile 32x48.
#define SA_STRIDE 40    // 32 + 8 pad (bf16)
#define SB_STRIDE 104   // 96 + 8 pad (bf16)

__global__ __launch_bounds__(256) void kGemm() {
    __shared__ __nv_bfloat16 s_a[128 * SA_STRIDE];
    __shared__ __nv_bfloat16 s_b[32 * SB_STRIDE];

    const int t = threadIdx.x, lane = t & 31, wid = t >> 5;
    const int wm = (wid & 3) * 32;         // warp M offset
    const int wn = (wid >> 2) * 48;        // warp N offset
    const int m0 = blockIdx.x * 128;
    const int n0 = blockIdx.y * 96;

    float acc[2][6][4];
    #pragma unroll
    for (int i = 0; i < 2; i++)
        #pragma unroll
        for (int j = 0; j < 6; j++)
            #pragma unroll
            for (int k = 0; k < 4; k++) acc[i][j][k] = 0.f;

    const uint32_t sa_base = (uint32_t)__cvta_generic_to_shared(s_a);
    const uint32_t sb_base = (uint32_t)__cvta_generic_to_shared(s_b);

    // per-lane ldmatrix address components
    const int a_row = lane & 15, a_hi = lane >> 4;      // A: rows, k-half
    const int b_k   = lane & 15, b_hi = lane >> 4;      // B: k-rows, n-half

    for (int it = 0; it < 9; it++) {
        const int kb = it * 32;
        __syncthreads();
        // stage A: 128 rows x 32 k  (512 x 16B chunks)
        #pragma unroll
        for (int ch = t; ch < 512; ch += 256) {
            int row = ch >> 2, q = ch & 3;
            uint4 d = *(const uint4*)(g_ab + (size_t)(m0 + row)*KDIM + kb + q*8);
            *(uint4*)(s_a + row*SA_STRIDE + q*8) = d;
        }
        // stage B: 32 k-rows x 96 n  (384 x 16B chunks)
        for (int ch = t; ch < 384; ch += 256) {
            int kr = ch / 12, q = ch % 12;
            uint4 d = *(const uint4*)(g_Bm + (size_t)(kb + kr)*NDIM + n0 + q*8);
            *(uint4*)(s_b + kr*SB_STRIDE + q*8) = d;
        }
        __syncthreads();

        #pragma unroll
        for (int k16 = 0; k16 < 2; k16++) {
            const int kk = k16 * 16;
            uint32_t afr[2][4], bfr[3][4];
            #pragma unroll
            for (int mi = 0; mi < 2; mi++) {
                uint32_t addr = sa_base +
                    ((wm + mi*16 + a_row) * SA_STRIDE + kk + a_hi*8) * 2;
                ldsm4(afr[mi], addr);
            }
            #pragma unroll
            for (int nb = 0; nb < 3; nb++) {
                uint32_t addr = sb_base +
                    ((kk + b_k) * SB_STRIDE + wn + nb*16 + b_hi*8) * 2;
                ldsm4t(bfr[nb], addr);
            }
            #pragma unroll
            for (int mi = 0; mi < 2; mi++)
                #pragma unroll
                for (int ni = 0; ni < 6; ni++)
                    mma16816(acc[mi][ni], afr[mi],
                             bfr[ni>>1][(ni&1)*2], bfr[ni>>1][(ni&1)*2 + 1]);
        }
    }

    // epilogue: cols<256 -> g_v bf16 ; cols>=256 -> g_s1p fp32
    #pragma unroll
    for (int mi = 0; mi < 2; mi++) {
        const int rb = m0 + wm + mi*16 + (lane >> 2);
        #pragma unroll
        for (int ni = 0; ni < 6; ni++) {
            const int gc = n0 + wn + ni*8 + (lane & 3)*2;
            float* a4 = acc[mi][ni];
            if (gc < 256) {
                *(__nv_bfloat162*)(g_v + (size_t)rb*256 + gc)
                    = __floats2bfloat162_rn(a4[0], a4[1]);
                *(__nv_bfloat162*)(g_v + (size_t)(rb+8)*256 + gc)
                    = __floats2bfloat162_rn(a4[2], a4[3]);
            } else {
                int jc = gc - 256;
                g_s1p[(size_t)rb*32 + jc]       = a4[0];
                g_s1p[(size_t)rb*32 + jc + 1]   = a4[1];
                g_s1p[(size_t)(rb+8)*32 + jc]     = a4[2];
                g_s1p[(size_t)(rb+8)*32 + jc + 1] = a4[3];
            }
        }
    }
}

// ---------------- kAttn: slim per-token attention ----------------
// Shared (float idx): s_w bf16[128*256] @0 (16384 f), s_s1 @16384 (4096),
// s_xln @20480 (256), s_qs @20736 (32), s_vis @20768 (128), s_red @20896 (8)
#define ATTN_SMEM_FLOATS 20904
#define ATTN_SMEM_BYTES  (ATTN_SMEM_FLOATS * 4)

__global__ __launch_bounds__(256, 2) void kAttn(
    const float* __restrict__ query, const int* __restrict__ vis,
    const float* __restrict__ ln1_g, const float* __restrict__ ln1_b,
    const float* __restrict__ sc_w2, const float* __restrict__ sc_b2,
    const float* __restrict__ pos_b2)
{
    extern __shared__ float sm[];
    __nv_bfloat16* s_w   = (__nv_bfloat16*)sm;
    float*         s_s1  = sm + 16384;
    float*         s_xln = sm + 20480;
    float*         s_qs  = sm + 20736;
    int*           s_vis = (int*)(sm + 20768);
    float*         s_red = sm + 20896;

    const int bh = blockIdx.x, tid = threadIdx.x;
    const int lane = tid & 31, wid = tid >> 5;

    // LN1 on the query row
    float qv = query[bh*256 + tid];
    float m  = brsum(qv, s_red) * (1.f/256.f);
    float dv = qv - m;
    float var = brsum(dv*dv, s_red) * (1.f/256.f);
    float rstd = rsqrtf(var + 1e-6f);
    s_xln[tid] = dv * rstd * ln1_g[tid] + ln1_b[tid];
    __syncthreads();

    // stage s1pre + vis; warp0 computes qs = xln @ Wqs
    {
        const float4* sp = (const float4*)(g_s1p + (size_t)bh * 4096);
        float4* dp = (float4*)s_s1;
        #pragma unroll
        for (int i = 0; i < 4; i++) dp[tid + i*256] = sp[tid + i*256];
        if (tid < 128) s_vis[tid] = vis[bh*128 + tid];
        if (wid == 0) {
            float a = 0.f;
            #pragma unroll 4
            for (int c = 0; c < 256; c++) a += s_xln[c] * g_Wqs[c*32 + lane];
            s_qs[lane] = a;
        }
    }
    __syncthreads();

    // s1 = relu(s1pre + cb - qs)  in place
    #pragma unroll
    for (int i = 0; i < 16; i++) {
        int o = tid + i*256, j = o & 31;
        s_s1[o] = fmaxf(s_s1[o] + g_cb[j] - s_qs[j], 0.f);
    }
    __syncthreads();

    // logits (thread <-> channel c), masked, bf16 in s_w
    const int c = tid;
    {
        float w2r[32];
        #pragma unroll
        for (int j = 0; j < 32; j++) w2r[j] = sc_w2[j*256 + c];
        const float sb2 = sc_b2[c];
        for (int n = 0; n < 128; n++) {
            const float* s1r = s_s1 + n*32;
            float acc = sb2;
            #pragma unroll
            for (int j = 0; j < 32; j++) acc += s1r[j] * w2r[j];
            float l = (s_vis[n] == 0) ? -1e9f : acc;
            s_w[n*256 + c] = __float2bfloat16(l);
        }
    }

    // per-channel softmax (column is thread-private; no syncs needed)
    float mx = -3e38f;
    #pragma unroll 4
    for (int n = 0; n < 128; n++)
        mx = fmaxf(mx, __bfloat162float(s_w[n*256 + c]));
    float s = 0.f;
    #pragma unroll 4
    for (int n = 0; n < 128; n++) {
        float l = __bfloat162float(s_w[n*256 + c]);
        __nv_bfloat16 eb = __float2bfloat16(__expf(l - mx));
        s_w[n*256 + c] = eb;
        s += __bfloat162float(eb);
    }

    // weighted reduce against global v' (coalesced bf16 column reads)
    float aggv = 0.f;
    const __nv_bfloat16* vp = g_v + (size_t)bh * 32768 + c;
    #pragma unroll 8
    for (int n = 0; n < 128; n++) {
        float w  = __bfloat162float(s_w[n*256 + c]);
        float vv = __bfloat162float(vp[(size_t)n * 256]);
        aggv += w * vv;
    }
    g_agg[bh*256 + c] = aggv / s + pos_b2[c];
}

// ---------------- kOut: agg@Wo + bo + query residual, then LN2 ----------------
__global__ __launch_bounds__(256) void kOut(
    const float* __restrict__ query, const float* __restrict__ Wo,
    const float* __restrict__ bo,
    const float* __restrict__ ln2_g, const float* __restrict__ ln2_b)
{
    __shared__ float s_a[256];
    __shared__ float s_red[8];
    const int bh = blockIdx.x, c = threadIdx.x;
    s_a[c] = g_agg[bh*256 + c];
    __syncthreads();
    float acc = bo[c];
    #pragma unroll 4
    for (int d = 0; d < 256; d += 4) {
        float4 a4 = *(const float4*)(s_a + d);
        acc += a4.x*Wo[(d+0)*256 + c];
        acc += a4.y*Wo[(d+1)*256 + c];
        acc += a4.z*Wo[(d+2)*256 + c];
        acc += a4.w*Wo[(d+3)*256 + c];
    }
    float x2 = acc + query[bh*256 + c];
    g_x[bh*256 + c] = x2;
    float m = brsum(x2, s_red) * (1.f/256.f);
    float dv = x2 - m;
    float var = brsum(dv*dv, s_red) * (1.f/256.f);
    float rstd = rsqrtf(var + 1e-6f);
    g_xln[bh*256 + c] = dv * rstd * ln2_g[c] + ln2_b[c];
}

// ---------------- kFF1: 4 tokens per block, h = relu(xln @ ff_w1 + b1) ----------------
__global__ __launch_bounds__(256) void kFF1(
    const float* __restrict__ ff_w1, const float* __restrict__ ff_b1)
{
    __shared__ float s_x[4*256];
    const int blk = blockIdx.x, tid = threadIdx.x;
    ((float4*)s_x)[tid] = ((const float4*)(g_xln + (size_t)blk*1024))[tid];
    __syncthreads();
    const int c0 = tid * 4;
    float4 b4 = *(const float4*)(ff_b1 + c0);
    float4 a0 = b4, a1 = b4, a2 = b4, a3 = b4;
    #pragma unroll 4
    for (int d = 0; d < 256; d++) {
        float4 w4 = *(const float4*)(ff_w1 + d*1024 + c0);
        float x0 = s_x[d], x1 = s_x[256+d], x2 = s_x[512+d], x3 = s_x[768+d];
        a0.x += x0*w4.x; a0.y += x0*w4.y; a0.z += x0*w4.z; a0.w += x0*w4.w;
        a1.x += x1*w4.x; a1.y += x1*w4.y; a1.z += x1*w4.z; a1.w += x1*w4.w;
        a2.x += x2*w4.x; a2.y += x2*w4.y; a2.z += x2*w4.z; a2.w += x2*w4.w;
        a3.x += x3*w4.x; a3.y += x3*w4.y; a3.z += x3*w4.z; a3.w += x3*w4.w;
    }
    a0.x = fmaxf(a0.x,0.f); a0.y = fmaxf(a0.y,0.f); a0.z = fmaxf(a0.z,0.f); a0.w = fmaxf(a0.w,0.f);
    a1.x = fmaxf(a1.x,0.f); a1.y = fmaxf(a1.y,0.f); a1.z = fmaxf(a1.z,0.f); a1.w = fmaxf(a1.w,0.f);
    a2.x = fmaxf(a2.x,0.f); a2.y = fmaxf(a2.y,0.f); a2.z = fmaxf(a2.z,0.f); a2.w = fmaxf(a2.w,0.f);
    a3.x = fmaxf(a3.x,0.f); a3.y = fmaxf(a3.y,0.f); a3.z = fmaxf(a3.z,0.f); a3.w = fmaxf(a3.w,0.f);
    float* hh = g_hh + (size_t)blk*4096;
    *(float4*)(hh + 0*1024 + c0) = a0;
    *(float4*)(hh + 1*1024 + c0) = a1;
    *(float4*)(hh + 2*1024 + c0) = a2;
    *(float4*)(hh + 3*1024 + c0) = a3;
}

// ---------------- kFF2: out = h @ ff_w2 + ff_b2 + x ----------------
__global__ __launch_bounds__(256) void kFF2(
    const float* __restrict__ ff_w2, const float* __restrict__ ff_b2,
    float* __restrict__ out)
{
    __shared__ float s_h[4*1024];
    const int blk = blockIdx.x, tid = threadIdx.x;
    const float4* src = (const float4*)(g_hh + (size_t)blk*4096);
    float4* dst = (float4*)s_h;
    #pragma unroll
    for (int i = 0; i < 4; i++) dst[tid + i*256] = src[tid + i*256];
    __syncthreads();
    const int lr = tid >> 6;             // local row 0..3
    const int r  = blk*4 + lr;           // token
    const int c0 = (tid & 63) * 4;
    float4 acc = *(const float4*)(ff_b2 + c0);
    const float* hr = s_h + lr*1024;
    #pragma unroll 4
    for (int d = 0; d < 1024; d++) {
        float hv = hr[d];
        float4 w4 = *(const float4*)(ff_w2 + d*256 + c0);
        acc.x += hv*w4.x; acc.y += hv*w4.y; acc.z += hv*w4.z; acc.w += hv*w4.w;
    }
    float4 xr = *(const float4*)(g_x + r*256 + c0);
    acc.x += xr.x; acc.y += xr.y; acc.z += xr.z; acc.w += xr.w;
    *(float4*)(out + r*256 + c0) = acc;
}

// ---------------- launch ----------------
extern "C" void kernel_launch(void* const* d_in, const int* in_sizes, int n_in,
                              void* d_out, int out_size) {
    (void)in_sizes; (void)n_in; (void)out_size;
    const float* query  = (const float*)d_in[0];
    const float* key    = (const float*)d_in[1];
    const float* rel    = (const float*)d_in[2];
    const int*   vis    = (const int*)  d_in[3];
    const float* ln1_g  = (const float*)d_in[4];
    const float* ln1_b  = (const float*)d_in[5];
    const float* ln2_g  = (const float*)d_in[6];
    const float* ln2_b  = (const float*)d_in[7];
    const float* Wq     = (const float*)d_in[8];
    const float* Wk     = (const float*)d_in[9];
    const float* Wv     = (const float*)d_in[10];
    const float* pos_w1 = (const float*)d_in[11];
    const float* pos_b1 = (const float*)d_in[12];
    const float* pos_w2 = (const float*)d_in[13];
    const float* pos_b2 = (const float*)d_in[14];
    const float* sc_w1  = (const float*)d_in[15];
    const float* sc_b1  = (const float*)d_in[16];
    const float* sc_w2  = (const float*)d_in[17];
    const float* sc_b2  = (const float*)d_in[18];
    const float* Wo     = (const float*)d_in[19];
    const float* bo     = (const float*)d_in[20];
    const float* ff_w1  = (const float*)d_in[21];
    const float* ff_b1  = (const float*)d_in[22];
    const float* ff_w2  = (const float*)d_in[23];
    const float* ff_b2  = (const float*)d_in[24];
    float* out = (float*)d_out;

    cudaFuncSetAttribute(kAttn, cudaFuncAttributeMaxDynamicSharedMemorySize, ATTN_SMEM_BYTES);

    kFold<<<65, 256>>>(Wq, Wk, sc_w1, sc_b1, pos_w2, pos_b2);
    kPrep<<<BHTOK + 1, 256>>>(key, rel, pos_w1, pos_b1, Wv, pos_w2);
    kGemm<<<dim3(1024, 3), 256>>>();
    kAttn<<<BHTOK, 256, ATTN_SMEM_BYTES>>>(query, vis, ln1_g, ln1_b, sc_w2, sc_b2, pos_b2);
    kOut<<<BHTOK, 256>>>(query, Wo, bo, ln2_g, ln2_b);
    kFF1<<<BHTOK/4, 256>>>(ff_w1, ff_b1);
    kFF2<<<BHTOK/4, 256>>>(ff_w2, ff_b2, out);
}

// round 12
// speedup vs baseline: 1.9089x; 1.1618x over previous
#include <cuda_runtime.h>
#include <cuda_bf16.h>
#include <stdint.h>

// Shapes
#define BHTOK 1024   // B*H
#define NKEY  128
#define CDIM  256
#define C8    32
#define HIDF  1024
#define MTOT  (BHTOK*NKEY)   // 131072
#define KDIM  288            // 256 key + 32 h1
#define NDIM  288            // 256 v' + 32 s1pre'

typedef unsigned long long ULL;

// ---------------- device scratch ----------------
__device__ float g_Wks[CDIM*C8];    // Wk @ sc_w1
__device__ float g_Wqs[CDIM*C8];    // Wq @ sc_w1
__device__ float g_Pws[C8*C8];      // pos_w2 @ sc_w1
__device__ float g_cb [C8];         // pos_b2 @ sc_w1 + sc_b1
__device__ __nv_bfloat16 g_h1[(size_t)MTOT*C8];     // h1 bf16 (8.4 MB)
__device__ __nv_bfloat16 g_Bm[KDIM*NDIM];           // B = [[Wv|Wks],[pos_w2|Pws]]
__device__ __nv_bfloat16 g_v [(size_t)MTOT*CDIM];   // v + pos - pos_b2 (67 MB)
__device__ float g_s1p[(size_t)MTOT*C8];            // s1 pre-activation (partial)
__device__ float g_agg[BHTOK*CDIM];
__device__ float g_x  [BHTOK*CDIM];
__device__ float g_xln[BHTOK*CDIM];
__device__ float g_hh [BHTOK*HIDF];

// ---------------- helpers ----------------
__device__ __forceinline__ float brsum(float v, float* sred) {
    #pragma unroll
    for (int o = 16; o > 0; o >>= 1) v += __shfl_down_sync(0xffffffffu, v, o);
    __syncthreads();
    if ((threadIdx.x & 31) == 0) sred[threadIdx.x >> 5] = v;
    __syncthreads();
    float s = 0.f;
    #pragma unroll
    for (int i = 0; i < 8; i++) s += sred[i];
    return s;
}
__device__ __forceinline__ void upk2(ULL v, float& lo, float& hi) {
    asm("mov.b64 {%0,%1}, %2;" : "=f"(lo), "=f"(hi) : "l"(v));
}
__device__ __forceinline__ void ffma2(ULL& d, ULL a, ULL b) {
    asm("fma.rn.f32x2 %0, %1, %2, %0;" : "+l"(d) : "l"(a), "l"(b));
}
__device__ __forceinline__ void ldsm4(uint32_t* r, uint32_t addr) {
    asm volatile("ldmatrix.sync.aligned.m8n8.x4.shared.b16 {%0,%1,%2,%3}, [%4];"
        : "=r"(r[0]), "=r"(r[1]), "=r"(r[2]), "=r"(r[3]) : "r"(addr));
}
__device__ __forceinline__ void ldsm4t(uint32_t* r, uint32_t addr) {
    asm volatile("ldmatrix.sync.aligned.m8n8.x4.trans.shared.b16 {%0,%1,%2,%3}, [%4];"
        : "=r"(r[0]), "=r"(r[1]), "=r"(r[2]), "=r"(r[3]) : "r"(addr));
}
__device__ __forceinline__ void mma16816(float* c, const uint32_t* a,
                                         uint32_t b0, uint32_t b1) {
    asm volatile("mma.sync.aligned.m16n8k16.row.col.f32.bf16.bf16.f32 "
        "{%0,%1,%2,%3}, {%4,%5,%6,%7}, {%8,%9}, {%0,%1,%2,%3};"
        : "+f"(c[0]), "+f"(c[1]), "+f"(c[2]), "+f"(c[3])
        : "r"(a[0]), "r"(a[1]), "r"(a[2]), "r"(a[3]), "r"(b0), "r"(b1));
}

// ---------------- kFold ----------------
__global__ __launch_bounds__(256) void kFold(
    const float* __restrict__ Wq, const float* __restrict__ Wk,
    const float* __restrict__ sc_w1, const float* __restrict__ sc_b1,
    const float* __restrict__ pos_w2, const float* __restrict__ pos_b2)
{
    int b = blockIdx.x, t = threadIdx.x;
    if (b < 64) {
        const float* W = (b < 32) ? Wk : Wq;
        float* dst     = (b < 32) ? g_Wks : g_Wqs;
        int o = (b & 31) * 256 + t;
        int d = o >> 5, j = o & 31;
        float a = 0.f;
        #pragma unroll 4
        for (int c = 0; c < 256; c++) a += W[d*256 + c] * sc_w1[c*32 + j];
        dst[o] = a;
    } else {
        #pragma unroll
        for (int k = 0; k < 4; k++) {
            int o = t + (k << 8);
            int tt = o >> 5, j = o & 31;
            float a = 0.f;
            #pragma unroll 4
            for (int c = 0; c < 256; c++) a += pos_w2[tt*256 + c] * sc_w1[c*32 + j];
            g_Pws[o] = a;
        }
        if (t < 32) {
            float a = sc_b1[t];
            #pragma unroll 4
            for (int c = 0; c < 256; c++) a += pos_b2[c] * sc_w1[c*32 + t];
            g_cb[t] = a;
        }
    }
}

// ---------------- kPrep: h1 bf16 + B matrix ----------------
__global__ __launch_bounds__(256) void kPrep(
    const float* __restrict__ rel,
    const float* __restrict__ pos_w1, const float* __restrict__ pos_b1,
    const float* __restrict__ Wv, const float* __restrict__ pos_w2)
{
    int b = blockIdx.x, t = threadIdx.x;
    if (b < BHTOK) {
        #pragma unroll
        for (int i = 0; i < 16; i++) {
            int o = t + i * 256;                // o = n*32 + tt
            int n = o >> 5, tt = o & 31;
            const float* rp = rel + (size_t)(b*128 + n) * 4;
            float a = pos_b1[tt];
            a += rp[0]*pos_w1[0*32 + tt];
            a += rp[1]*pos_w1[1*32 + tt];
            a += rp[2]*pos_w1[2*32 + tt];
            a += rp[3]*pos_w1[3*32 + tt];
            g_h1[((size_t)(b*128 + n))*32 + tt] = __float2bfloat16(fmaxf(a, 0.f));
        }
    } else {
        for (int idx = t; idx < KDIM*NDIM; idx += 256) {
            int r = idx / NDIM, c = idx % NDIM;
            float v;
            if (r < 256) v = (c < 256) ? Wv[r*256 + c]           : g_Wks[r*32 + (c-256)];
            else         v = (c < 256) ? pos_w2[(r-256)*256 + c] : g_Pws[(r-256)*32 + (c-256)];
            g_Bm[idx] = __float2bfloat16(v);
        }
    }
}

// ---------------- kGemm: C[131072,288] = [key|h1] @ B ----------------
// BM=128, BN=96, BK=32. Warps 4(M) x 2(N). Reads key fp32 directly, converts
// during STS; register prefetch pipeline. grid (3, 1024), x fastest -> the 3
// n-blocks that share a key tile run adjacently (L2 reuse).
#define SA_STRIDE 40    // 32 + 8 pad (bf16)
#define SB_STRIDE 104   // 96 + 8 pad (bf16)

__global__ __launch_bounds__(256, 2) void kGemm(const float* __restrict__ key) {
    __shared__ __align__(16) __nv_bfloat16 s_a[128 * SA_STRIDE];
    __shared__ __align__(16) __nv_bfloat16 s_b[32 * SB_STRIDE];

    const int t = threadIdx.x, lane = t & 31, wid = t >> 5;
    const int wm = (wid & 3) * 32;
    const int wn = (wid >> 2) * 48;
    const int n0 = blockIdx.x * 96;
    const int m0 = blockIdx.y * 128;

    float acc[2][6][4];
    #pragma unroll
    for (int i = 0; i < 2; i++)
        #pragma unroll
        for (int j = 0; j < 6; j++)
            #pragma unroll
            for (int k = 0; k < 4; k++) acc[i][j][k] = 0.f;

    const uint32_t sa_base = (uint32_t)__cvta_generic_to_shared(s_a);
    const uint32_t sb_base = (uint32_t)__cvta_generic_to_shared(s_b);
    const int a_row = lane & 15, a_hi = lane >> 4;
    const int b_k   = lane & 15, b_hi = lane >> 4;

    // pipeline registers
    float4 ra[4];        // key tile fragment (16 fp32)
    uint4  rb[2];        // B tile fragment
    uint4  rh[2];        // h1 tile fragment (last iter)

    // ---- load tile 0 ----
    #pragma unroll
    for (int i = 0; i < 4; i++) {
        int ch = t + i*256, row = ch >> 3, q = ch & 7;
        ra[i] = *(const float4*)(key + (size_t)(m0+row)*256 + q*4);
    }
    #pragma unroll
    for (int i = 0; i < 2; i++) {
        int ch = t + i*256;
        if (ch < 384) {
            int kr = ch / 12, q = ch % 12;
            rb[i] = *(const uint4*)(g_Bm + (size_t)kr*NDIM + n0 + q*8);
        }
    }

    for (int it = 0; it < 8; it++) {
        // store staged tile
        #pragma unroll
        for (int i = 0; i < 4; i++) {
            int ch = t + i*256, row = ch >> 3, q = ch & 7;
            __nv_bfloat162* d = (__nv_bfloat162*)(s_a + row*SA_STRIDE + q*4);
            d[0] = __floats2bfloat162_rn(ra[i].x, ra[i].y);
            d[1] = __floats2bfloat162_rn(ra[i].z, ra[i].w);
        }
        #pragma unroll
        for (int i = 0; i < 2; i++) {
            int ch = t + i*256;
            if (ch < 384) {
                int kr = ch / 12, q = ch % 12;
                *(uint4*)(s_b + kr*SB_STRIDE + q*8) = rb[i];
            }
        }
        __syncthreads();

        // prefetch next tile
        if (it < 7) {
            const int kb = (it+1) * 32;
            #pragma unroll
            for (int i = 0; i < 4; i++) {
                int ch = t + i*256, row = ch >> 3, q = ch & 7;
                ra[i] = *(const float4*)(key + (size_t)(m0+row)*256 + kb + q*4);
            }
            #pragma unroll
            for (int i = 0; i < 2; i++) {
                int ch = t + i*256;
                if (ch < 384) {
                    int kr = ch / 12, q = ch % 12;
                    rb[i] = *(const uint4*)(g_Bm + (size_t)(kb+kr)*NDIM + n0 + q*8);
                }
            }
        } else {
            // prefetch last (h1) tile
            #pragma unroll
            for (int i = 0; i < 2; i++) {
                int ch = t + i*256, row = ch >> 2, q = ch & 3;
                rh[i] = ((const uint4*)(g_h1 + (size_t)(m0+row)*32))[q];
            }
            #pragma unroll
            for (int i = 0; i < 2; i++) {
                int ch = t + i*256;
                if (ch < 384) {
                    int kr = ch / 12, q = ch % 12;
                    rb[i] = *(const uint4*)(g_Bm + (size_t)(256+kr)*NDIM + n0 + q*8);
                }
            }
        }

        // compute on staged tile
        #pragma unroll
        for (int k16 = 0; k16 < 2; k16++) {
            const int kk = k16 * 16;
            uint32_t afr[2][4], bfr[3][4];
            #pragma unroll
            for (int mi = 0; mi < 2; mi++)
                ldsm4(afr[mi], sa_base + ((wm + mi*16 + a_row)*SA_STRIDE + kk + a_hi*8)*2);
            #pragma unroll
            for (int nb = 0; nb < 3; nb++)
                ldsm4t(bfr[nb], sb_base + ((kk + b_k)*SB_STRIDE + wn + nb*16 + b_hi*8)*2);
            #pragma unroll
            for (int mi = 0; mi < 2; mi++)
                #pragma unroll
                for (int ni = 0; ni < 6; ni++)
                    mma16816(acc[mi][ni], afr[mi],
                             bfr[ni>>1][(ni&1)*2], bfr[ni>>1][(ni&1)*2 + 1]);
        }
        __syncthreads();
    }

    // ---- last iter: h1 tile ----
    #pragma unroll
    for (int i = 0; i < 2; i++) {
        int ch = t + i*256, row = ch >> 2, q = ch & 3;
        *(uint4*)(s_a + row*SA_STRIDE + q*8) = rh[i];
    }
    #pragma unroll
    for (int i = 0; i < 2; i++) {
        int ch = t + i*256;
        if (ch < 384) {
            int kr = ch / 12, q = ch % 12;
            *(uint4*)(s_b + kr*SB_STRIDE + q*8) = rb[i];
        }
    }
    __syncthreads();
    #pragma unroll
    for (int k16 = 0; k16 < 2; k16++) {
        const int kk = k16 * 16;
        uint32_t afr[2][4], bfr[3][4];
        #pragma unroll
        for (int mi = 0; mi < 2; mi++)
            ldsm4(afr[mi], sa_base + ((wm + mi*16 + a_row)*SA_STRIDE + kk + a_hi*8)*2);
        #pragma unroll
        for (int nb = 0; nb < 3; nb++)
            ldsm4t(bfr[nb], sb_base + ((kk + b_k)*SB_STRIDE + wn + nb*16 + b_hi*8)*2);
        #pragma unroll
        for (int mi = 0; mi < 2; mi++)
            #pragma unroll
            for (int ni = 0; ni < 6; ni++)
                mma16816(acc[mi][ni], afr[mi],
                         bfr[ni>>1][(ni&1)*2], bfr[ni>>1][(ni&1)*2 + 1]);
    }

    // epilogue: cols<256 -> g_v bf16 ; cols>=256 -> g_s1p fp32
    #pragma unroll
    for (int mi = 0; mi < 2; mi++) {
        const int rb_ = m0 + wm + mi*16 + (lane >> 2);
        #pragma unroll
        for (int ni = 0; ni < 6; ni++) {
            const int gc = n0 + wn + ni*8 + (lane & 3)*2;
            float* a4 = acc[mi][ni];
            if (gc < 256) {
                *(__nv_bfloat162*)(g_v + (size_t)rb_*256 + gc)
                    = __floats2bfloat162_rn(a4[0], a4[1]);
                *(__nv_bfloat162*)(g_v + (size_t)(rb_+8)*256 + gc)
                    = __floats2bfloat162_rn(a4[2], a4[3]);
            } else {
                int jc = gc - 256;
                g_s1p[(size_t)rb_*32 + jc]        = a4[0];
                g_s1p[(size_t)rb_*32 + jc + 1]    = a4[1];
                g_s1p[(size_t)(rb_+8)*32 + jc]     = a4[2];
                g_s1p[(size_t)(rb_+8)*32 + jc + 1] = a4[3];
            }
        }
    }
}

// ---------------- kAttn: single-pass fused softmax + reduce ----------------
// thread = channel pair (p = tid&127, channels 2p,2p+1), n split into halves.
__global__ __launch_bounds__(256) void kAttn(
    const float* __restrict__ query, const int* __restrict__ vis,
    const float* __restrict__ ln1_g, const float* __restrict__ ln1_b,
    const float* __restrict__ sc_w2, const float* __restrict__ sc_b2,
    const float* __restrict__ pos_b2)
{
    __shared__ float s_s1d[128*64];   // s1 values duplicated as pairs (32 KB)
    __shared__ float s_xln[256];
    __shared__ float s_qs[32];
    __shared__ int   s_vis[128];
    __shared__ float s_red[8];
    __shared__ float s_part[4][128];

    const int bh = blockIdx.x, tid = threadIdx.x;
    const int lane = tid & 31, wid = tid >> 5;

    // LN1
    float qv = query[bh*256 + tid];
    float m = brsum(qv, s_red) * (1.f/256.f);
    float dvv = qv - m;
    float var = brsum(dvv*dvv, s_red) * (1.f/256.f);
    s_xln[tid] = dvv * rsqrtf(var + 1e-6f) * ln1_g[tid] + ln1_b[tid];
    if (tid < 128) s_vis[tid] = vis[bh*128 + tid];
    __syncthreads();

    if (wid == 0) {
        float a = 0.f;
        #pragma unroll 4
        for (int c = 0; c < 256; c++) a += s_xln[c] * g_Wqs[c*32 + lane];
        s_qs[lane] = a;
    }
    __syncthreads();

    // s1 = relu(s1pre + cb - qs), stored duplicated for f32x2
    {
        const float4* sp = (const float4*)(g_s1p + (size_t)bh * 4096);
        #pragma unroll
        for (int i = 0; i < 4; i++) {
            int i4 = tid + i*256;               // float4 index
            int n = i4 >> 3, jb = (i4 & 7) * 4; // 4 consecutive j
            float4 v4 = sp[i4];
            float a0 = fmaxf(v4.x + g_cb[jb+0] - s_qs[jb+0], 0.f);
            float a1 = fmaxf(v4.y + g_cb[jb+1] - s_qs[jb+1], 0.f);
            float a2 = fmaxf(v4.z + g_cb[jb+2] - s_qs[jb+2], 0.f);
            float a3 = fmaxf(v4.w + g_cb[jb+3] - s_qs[jb+3], 0.f);
            float4* dd = (float4*)(s_s1d + n*64 + jb*2);
            dd[0] = make_float4(a0, a0, a1, a1);
            dd[1] = make_float4(a2, a2, a3, a3);
        }
    }
    __syncthreads();

    const int p = tid & 127, half = tid >> 7;
    const int c0 = p * 2;
    ULL w2[32];
    #pragma unroll
    for (int j = 0; j < 32; j++) w2[j] = *(const ULL*)(sc_w2 + j*256 + c0);
    const ULL sb2 = *(const ULL*)(sc_b2 + c0);

    float sum0 = 0.f, sum1 = 0.f, agg0 = 0.f, agg1 = 0.f;
    const __nv_bfloat162* vbase = (const __nv_bfloat162*)(g_v + (size_t)bh*32768) + p;
    const int nb = half * 64;
    #pragma unroll 2
    for (int n = nb; n < nb + 64; n++) {
        const ulonglong2* s1r = (const ulonglong2*)(s_s1d + n*64);
        ULL acc = sb2;
        #pragma unroll
        for (int j2 = 0; j2 < 16; j2++) {
            ulonglong2 s2 = s1r[j2];
            ffma2(acc, s2.x, w2[j2*2]);
            ffma2(acc, s2.y, w2[j2*2 + 1]);
        }
        float l0, l1; upk2(acc, l0, l1);
        if (s_vis[n] == 0) { l0 = -30.f; l1 = -30.f; }
        float e0 = __expf(l0), e1 = __expf(l1);
        float2 vf = __bfloat1622float2(vbase[n*128]);
        sum0 += e0; sum1 += e1;
        agg0 += e0 * vf.x; agg1 += e1 * vf.y;
    }
    if (half) {
        s_part[0][p] = sum0; s_part[1][p] = sum1;
        s_part[2][p] = agg0; s_part[3][p] = agg1;
    }
    __syncthreads();
    if (!half) {
        sum0 += s_part[0][p]; sum1 += s_part[1][p];
        agg0 += s_part[2][p]; agg1 += s_part[3][p];
        float2 o;
        o.x = agg0 / sum0 + pos_b2[c0];
        o.y = agg1 / sum1 + pos_b2[c0 + 1];
        *(float2*)(g_agg + bh*256 + c0) = o;
    }
}

// ---------------- kOut: agg@Wo + bo + residual, then LN2 ----------------
__global__ __launch_bounds__(256) void kOut(
    const float* __restrict__ query, const float* __restrict__ Wo,
    const float* __restrict__ bo,
    const float* __restrict__ ln2_g, const float* __restrict__ ln2_b)
{
    __shared__ float s_a[256];
    __shared__ float s_red[8];
    const int bh = blockIdx.x, c = threadIdx.x;
    s_a[c] = g_agg[bh*256 + c];
    __syncthreads();
    float acc = bo[c];
    #pragma unroll 4
    for (int d = 0; d < 256; d += 4) {
        float4 a4 = *(const float4*)(s_a + d);
        acc += a4.x*Wo[(d+0)*256 + c];
        acc += a4.y*Wo[(d+1)*256 + c];
        acc += a4.z*Wo[(d+2)*256 + c];
        acc += a4.w*Wo[(d+3)*256 + c];
    }
    float x2 = acc + query[bh*256 + c];
    g_x[bh*256 + c] = x2;
    float m = brsum(x2, s_red) * (1.f/256.f);
    float dv = x2 - m;
    float var = brsum(dv*dv, s_red) * (1.f/256.f);
    float rstd = rsqrtf(var + 1e-6f);
    g_xln[bh*256 + c] = dv * rstd * ln2_g[c] + ln2_b[c];
}

// ---------------- kFF1: 8 tokens/block ----------------
__global__ __launch_bounds__(256) void kFF1(
    const float* __restrict__ ff_w1, const float* __restrict__ ff_b1)
{
    __shared__ float s_x[8*256];
    const int blk = blockIdx.x, tid = threadIdx.x;
    const float4* src = (const float4*)(g_xln + (size_t)blk*2048);
    #pragma unroll
    for (int i = 0; i < 2; i++) ((float4*)s_x)[tid + i*256] = src[tid + i*256];
    __syncthreads();
    const int c0 = tid * 4;
    float4 b4 = *(const float4*)(ff_b1 + c0);
    float4 a[8];
    #pragma unroll
    for (int r = 0; r < 8; r++) a[r] = b4;
    #pragma unroll 2
    for (int d = 0; d < 256; d++) {
        float4 w4 = *(const float4*)(ff_w1 + d*1024 + c0);
        #pragma unroll
        for (int r = 0; r < 8; r++) {
            float xv = s_x[r*256 + d];
            a[r].x += xv*w4.x; a[r].y += xv*w4.y; a[r].z += xv*w4.z; a[r].w += xv*w4.w;
        }
    }
    #pragma unroll
    for (int r = 0; r < 8; r++) {
        a[r].x = fmaxf(a[r].x, 0.f); a[r].y = fmaxf(a[r].y, 0.f);
        a[r].z = fmaxf(a[r].z, 0.f); a[r].w = fmaxf(a[r].w, 0.f);
        *(float4*)(g_hh + (size_t)(blk*8 + r)*1024 + c0) = a[r];
    }
}

// ---------------- kFF2: 8 tokens/block, out = h @ ff_w2 + b2 + x ----------------
__global__ __launch_bounds__(256) void kFF2(
    const float* __restrict__ ff_w2, const float* __restrict__ ff_b2,
    float* __restrict__ out)
{
    __shared__ float s_h[8*1024];
    const int blk = blockIdx.x, tid = threadIdx.x;
    const float4* src = (const float4*)(g_hh + (size_t)blk*8192);
    #pragma unroll
    for (int i = 0; i < 8; i++) ((float4*)s_h)[tid + i*256] = src[tid + i*256];
    __syncthreads();
    const int lr0 = (tid >> 6) * 2;      // rows lr0, lr0+1
    const int c0  = (tid & 63) * 4;
    float4 b4 = *(const float4*)(ff_b2 + c0);
    float4 a0 = b4, a1 = b4;
    const float* h0 = s_h + lr0*1024;
    const float* h1 = s_h + (lr0+1)*1024;
    #pragma unroll 4
    for (int d = 0; d < 1024; d++) {
        float4 w4 = *(const float4*)(ff_w2 + d*256 + c0);
        float v0 = h0[d], v1 = h1[d];
        a0.x += v0*w4.x; a0.y += v0*w4.y; a0.z += v0*w4.z; a0.w += v0*w4.w;
        a1.x += v1*w4.x; a1.y += v1*w4.y; a1.z += v1*w4.z; a1.w += v1*w4.w;
    }
    const int r0 = blk*8 + lr0;
    float4 x0 = *(const float4*)(g_x + (size_t)r0*256 + c0);
    float4 x1 = *(const float4*)(g_x + (size_t)(r0+1)*256 + c0);
    a0.x += x0.x; a0.y += x0.y; a0.z += x0.z; a0.w += x0.w;
    a1.x += x1.x; a1.y += x1.y; a1.z += x1.z; a1.w += x1.w;
    *(float4*)(out + (size_t)r0*256 + c0)     = a0;
    *(float4*)(out + (size_t)(r0+1)*256 + c0) = a1;
}

// ---------------- launch ----------------
extern "C" void kernel_launch(void* const* d_in, const int* in_sizes, int n_in,
                              void* d_out, int out_size) {
    (void)in_sizes; (void)n_in; (void)out_size;
    const float* query  = (const float*)d_in[0];
    const float* key    = (const float*)d_in[1];
    const float* rel    = (const float*)d_in[2];
    const int*   vis    = (const int*)  d_in[3];
    const float* ln1_g  = (const float*)d_in[4];
    const float* ln1_b  = (const float*)d_in[5];
    const float* ln2_g  = (const float*)d_in[6];
    const float* ln2_b  = (const float*)d_in[7];
    const float* Wq     = (const float*)d_in[8];
    const float* Wk     = (const float*)d_in[9];
    const float* Wv     = (const float*)d_in[10];
    const float* pos_w1 = (const float*)d_in[11];
    const float* pos_b1 = (const float*)d_in[12];
    const float* pos_w2 = (const float*)d_in[13];
    const float* pos_b2 = (const float*)d_in[14];
    const float* sc_w1  = (const float*)d_in[15];
    const float* sc_b1  = (const float*)d_in[16];
    const float* sc_w2  = (const float*)d_in[17];
    const float* sc_b2  = (const float*)d_in[18];
    const float* Wo     = (const float*)d_in[19];
    const float* bo     = (const float*)d_in[20];
    const float* ff_w1  = (const float*)d_in[21];
    const float* ff_b1  = (const float*)d_in[22];
    const float* ff_w2  = (const float*)d_in[23];
    const float* ff_b2  = (const float*)d_in[24];
    float* out = (float*)d_out;

    kFold<<<65, 256>>>(Wq, Wk, sc_w1, sc_b1, pos_w2, pos_b2);
    kPrep<<<BHTOK + 1, 256>>>(rel, pos_w1, pos_b1, Wv, pos_w2);
    kGemm<<<dim3(3, 1024), 256>>>(key);
    kAttn<<<BHTOK, 256>>>(query, vis, ln1_g, ln1_b, sc_w2, sc_b2, pos_b2);
    kOut<<<BHTOK, 256>>>(query, Wo, bo, ln2_g, ln2_b);
    kFF1<<<BHTOK/8, 256>>>(ff_w1, ff_b1);
    kFF2<<<BHTOK/8, 256>>>(ff_w2, ff_b2, out);
}

// round 16
// speedup vs baseline: 2.2587x; 1.1833x over previous
#include <cuda_runtime.h>
#include <cuda_bf16.h>
#include <stdint.h>

// Shapes
#define BHTOK 1024   // B*H
#define NKEY  128
#define CDIM  256
#define C8    32
#define HIDF  1024
#define MTOT  (BHTOK*NKEY)   // 131072
#define KDIM  288
#define NDIM  288

typedef unsigned long long ULL;

// ---------------- device scratch ----------------
__device__ float g_Wks[CDIM*C8];
__device__ float g_Wqs[CDIM*C8];
__device__ float g_Pws[C8*C8];
__device__ float g_cb [C8];
__device__ __nv_bfloat16 g_h1[(size_t)MTOT*C8];     // h1 bf16
__device__ __nv_bfloat16 g_Bm[KDIM*NDIM];
__device__ __nv_bfloat16 g_v [(size_t)MTOT*CDIM];   // v + pos - pos_b2
__device__ float g_s1p[(size_t)MTOT*C8];
__device__ float g_agg[BHTOK*CDIM];
__device__ float g_x  [BHTOK*CDIM];                 // residual (fp32)
__device__ __nv_bfloat16 g_xlns[(size_t)BHTOK*768];       // [hi|lo|hi] LN2 out
__device__ __nv_bfloat16 g_hbs [(size_t)BHTOK*3072];      // [hi|lo|hi] relu(ff1)
__device__ __nv_bfloat16 g_w1s [(size_t)768*HIDF];        // [hi;hi;lo] ff_w1
__device__ __nv_bfloat16 g_w2s [(size_t)3072*CDIM];       // [hi;hi;lo] ff_w2

// ---------------- helpers ----------------
__device__ __forceinline__ float brsum(float v, float* sred) {
    #pragma unroll
    for (int o = 16; o > 0; o >>= 1) v += __shfl_down_sync(0xffffffffu, v, o);
    __syncthreads();
    if ((threadIdx.x & 31) == 0) sred[threadIdx.x >> 5] = v;
    __syncthreads();
    float s = 0.f;
    #pragma unroll
    for (int i = 0; i < 8; i++) s += sred[i];
    return s;
}
__device__ __forceinline__ void upk2(ULL v, float& lo, float& hi) {
    asm("mov.b64 {%0,%1}, %2;" : "=f"(lo), "=f"(hi) : "l"(v));
}
__device__ __forceinline__ void ffma2(ULL& d, ULL a, ULL b) {
    asm("fma.rn.f32x2 %0, %1, %2, %0;" : "+l"(d) : "l"(a), "l"(b));
}
__device__ __forceinline__ void fadd2(ULL& d, ULL a) {
    asm("add.rn.f32x2 %0, %0, %1;" : "+l"(d) : "l"(a));
}
__device__ __forceinline__ void ldsm4(uint32_t* r, uint32_t addr) {
    asm volatile("ldmatrix.sync.aligned.m8n8.x4.shared.b16 {%0,%1,%2,%3}, [%4];"
        : "=r"(r[0]), "=r"(r[1]), "=r"(r[2]), "=r"(r[3]) : "r"(addr));
}
__device__ __forceinline__ void ldsm4t(uint32_t* r, uint32_t addr) {
    asm volatile("ldmatrix.sync.aligned.m8n8.x4.trans.shared.b16 {%0,%1,%2,%3}, [%4];"
        : "=r"(r[0]), "=r"(r[1]), "=r"(r[2]), "=r"(r[3]) : "r"(addr));
}
__device__ __forceinline__ void mma16816(float* c, const uint32_t* a,
                                         uint32_t b0, uint32_t b1) {
    asm volatile("mma.sync.aligned.m16n8k16.row.col.f32.bf16.bf16.f32 "
        "{%0,%1,%2,%3}, {%4,%5,%6,%7}, {%8,%9}, {%0,%1,%2,%3};"
        : "+f"(c[0]), "+f"(c[1]), "+f"(c[2]), "+f"(c[3])
        : "r"(a[0]), "r"(a[1]), "r"(a[2]), "r"(a[3]), "r"(b0), "r"(b1));
}
__device__ __forceinline__ void bsplit(float v, __nv_bfloat16& h, __nv_bfloat16& l) {
    h = __float2bfloat16(v);
    l = __float2bfloat16(v - __bfloat162float(h));
}

// ---------------- kFold ----------------
__global__ __launch_bounds__(256) void kFold(
    const float* __restrict__ Wq, const float* __restrict__ Wk,
    const float* __restrict__ sc_w1, const float* __restrict__ sc_b1,
    const float* __restrict__ pos_w2, const float* __restrict__ pos_b2)
{
    int b = blockIdx.x, t = threadIdx.x;
    if (b < 64) {
        const float* W = (b < 32) ? Wk : Wq;
        float* dst     = (b < 32) ? g_Wks : g_Wqs;
        int o = (b & 31) * 256 + t;
        int d = o >> 5, j = o & 31;
        float a = 0.f;
        #pragma unroll 4
        for (int c = 0; c < 256; c++) a += W[d*256 + c] * sc_w1[c*32 + j];
        dst[o] = a;
    } else {
        #pragma unroll
        for (int k = 0; k < 4; k++) {
            int o = t + (k << 8);
            int tt = o >> 5, j = o & 31;
            float a = 0.f;
            #pragma unroll 4
            for (int c = 0; c < 256; c++) a += pos_w2[tt*256 + c] * sc_w1[c*32 + j];
            g_Pws[o] = a;
        }
        if (t < 32) {
            float a = sc_b1[t];
            #pragma unroll 4
            for (int c = 0; c < 256; c++) a += pos_b2[c] * sc_w1[c*32 + t];
            g_cb[t] = a;
        }
    }
}

// ---------------- kPrep: h1 bf16 + B matrix + split FF weights ----------------
__global__ __launch_bounds__(256) void kPrep(
    const float* __restrict__ rel,
    const float* __restrict__ pos_w1, const float* __restrict__ pos_b1,
    const float* __restrict__ Wv, const float* __restrict__ pos_w2,
    const float* __restrict__ ff_w1, const float* __restrict__ ff_w2)
{
    int b = blockIdx.x, t = threadIdx.x;
    if (b < BHTOK) {
        #pragma unroll
        for (int i = 0; i < 16; i++) {
            int o = t + i * 256;
            int n = o >> 5, tt = o & 31;
            const float* rp = rel + (size_t)(b*128 + n) * 4;
            float a = pos_b1[tt];
            a += rp[0]*pos_w1[0*32 + tt];
            a += rp[1]*pos_w1[1*32 + tt];
            a += rp[2]*pos_w1[2*32 + tt];
            a += rp[3]*pos_w1[3*32 + tt];
            g_h1[((size_t)(b*128 + n))*32 + tt] = __float2bfloat16(fmaxf(a, 0.f));
        }
    } else if (b == BHTOK) {
        for (int idx = t; idx < KDIM*NDIM; idx += 256) {
            int r = idx / NDIM, c = idx % NDIM;
            float v;
            if (r < 256) v = (c < 256) ? Wv[r*256 + c]           : g_Wks[r*32 + (c-256)];
            else         v = (c < 256) ? pos_w2[(r-256)*256 + c] : g_Pws[(r-256)*32 + (c-256)];
            g_Bm[idx] = __float2bfloat16(v);
        }
    } else {
        int wb = b - BHTOK - 1;     // 0..767
        __align__(16) __nv_bfloat16 o8[8];
        if (wb < 384) {
            // g_w1s: 768 x 1024 = [hi;hi;lo]
            size_t base = (size_t)wb * 2048 + (size_t)t * 8;
            int rp = (int)(base >> 10), c = (int)(base & 1023);
            const float* src = ff_w1 + (size_t)(rp & 255) * 1024 + c;
            float4 v0 = ((const float4*)src)[0];
            float4 v1 = ((const float4*)src)[1];
            float vv[8] = {v0.x,v0.y,v0.z,v0.w,v1.x,v1.y,v1.z,v1.w};
            bool lo = (rp >= 512);
            #pragma unroll
            for (int i = 0; i < 8; i++) {
                __nv_bfloat16 h, l; bsplit(vv[i], h, l);
                o8[i] = lo ? l : h;
            }
            *(uint4*)(g_w1s + base) = *(const uint4*)o8;
        } else {
            // g_w2s: 3072 x 256 = [hi;hi;lo]
            size_t base = (size_t)(wb - 384) * 2048 + (size_t)t * 8;
            int rp = (int)(base >> 8), c = (int)(base & 255);
            const float* src = ff_w2 + (size_t)(rp & 1023) * 256 + c;
            float4 v0 = ((const float4*)src)[0];
            float4 v1 = ((const float4*)src)[1];
            float vv[8] = {v0.x,v0.y,v0.z,v0.w,v1.x,v1.y,v1.z,v1.w};
            bool lo = (rp >= 2048);
            #pragma unroll
            for (int i = 0; i < 8; i++) {
                __nv_bfloat16 h, l; bsplit(vv[i], h, l);
                o8[i] = lo ? l : h;
            }
            *(uint4*)(g_w2s + base) = *(const uint4*)o8;
        }
    }
}

// ---------------- kGemm: C[131072,288] = [key|h1] @ B ----------------
#define SA_STRIDE 40
#define SB_STRIDE 104

__global__ __launch_bounds__(256, 2) void kGemm(const float* __restrict__ key) {
    __shared__ __align__(16) __nv_bfloat16 s_a[128 * SA_STRIDE];
    __shared__ __align__(16) __nv_bfloat16 s_b[32 * SB_STRIDE];

    const int t = threadIdx.x, lane = t & 31, wid = t >> 5;
    const int wm = (wid & 3) * 32;
    const int wn = (wid >> 2) * 48;
    const int n0 = blockIdx.x * 96;
    const int m0 = blockIdx.y * 128;

    float acc[2][6][4];
    #pragma unroll
    for (int i = 0; i < 2; i++)
        #pragma unroll
        for (int j = 0; j < 6; j++)
            #pragma unroll
            for (int k = 0; k < 4; k++) acc[i][j][k] = 0.f;

    const uint32_t sa_base = (uint32_t)__cvta_generic_to_shared(s_a);
    const uint32_t sb_base = (uint32_t)__cvta_generic_to_shared(s_b);
    const int a_row = lane & 15, a_hi = lane >> 4;
    const int b_k   = lane & 15, b_hi = lane >> 4;

    float4 ra[4];
    uint4  rb[2];
    uint4  rh[2];

    #pragma unroll
    for (int i = 0; i < 4; i++) {
        int ch = t + i*256, row = ch >> 3, q = ch & 7;
        ra[i] = *(const float4*)(key + (size_t)(m0+row)*256 + q*4);
    }
    #pragma unroll
    for (int i = 0; i < 2; i++) {
        int ch = t + i*256;
        if (ch < 384) {
            int kr = ch / 12, q = ch % 12;
            rb[i] = *(const uint4*)(g_Bm + (size_t)kr*NDIM + n0 + q*8);
        }
    }

    for (int it = 0; it < 8; it++) {
        #pragma unroll
        for (int i = 0; i < 4; i++) {
            int ch = t + i*256, row = ch >> 3, q = ch & 7;
            __nv_bfloat162* d = (__nv_bfloat162*)(s_a + row*SA_STRIDE + q*4);
            d[0] = __floats2bfloat162_rn(ra[i].x, ra[i].y);
            d[1] = __floats2bfloat162_rn(ra[i].z, ra[i].w);
        }
        #pragma unroll
        for (int i = 0; i < 2; i++) {
            int ch = t + i*256;
            if (ch < 384) {
                int kr = ch / 12, q = ch % 12;
                *(uint4*)(s_b + kr*SB_STRIDE + q*8) = rb[i];
            }
        }
        __syncthreads();

        if (it < 7) {
            const int kb = (it+1) * 32;
            #pragma unroll
            for (int i = 0; i < 4; i++) {
                int ch = t + i*256, row = ch >> 3, q = ch & 7;
                ra[i] = *(const float4*)(key + (size_t)(m0+row)*256 + kb + q*4);
            }
            #pragma unroll
            for (int i = 0; i < 2; i++) {
                int ch = t + i*256;
                if (ch < 384) {
                    int kr = ch / 12, q = ch % 12;
                    rb[i] = *(const uint4*)(g_Bm + (size_t)(kb+kr)*NDIM + n0 + q*8);
                }
            }
        } else {
            #pragma unroll
            for (int i = 0; i < 2; i++) {
                int ch = t + i*256, row = ch >> 2, q = ch & 3;
                rh[i] = ((const uint4*)(g_h1 + (size_t)(m0+row)*32))[q];
            }
            #pragma unroll
            for (int i = 0; i < 2; i++) {
                int ch = t + i*256;
                if (ch < 384) {
                    int kr = ch / 12, q = ch % 12;
                    rb[i] = *(const uint4*)(g_Bm + (size_t)(256+kr)*NDIM + n0 + q*8);
                }
            }
        }

        #pragma unroll
        for (int k16 = 0; k16 < 2; k16++) {
            const int kk = k16 * 16;
            uint32_t afr[2][4], bfr[3][4];
            #pragma unroll
            for (int mi = 0; mi < 2; mi++)
                ldsm4(afr[mi], sa_base + ((wm + mi*16 + a_row)*SA_STRIDE + kk + a_hi*8)*2);
            #pragma unroll
            for (int nb = 0; nb < 3; nb++)
                ldsm4t(bfr[nb], sb_base + ((kk + b_k)*SB_STRIDE + wn + nb*16 + b_hi*8)*2);
            #pragma unroll
            for (int mi = 0; mi < 2; mi++)
                #pragma unroll
                for (int ni = 0; ni < 6; ni++)
                    mma16816(acc[mi][ni], afr[mi],
                             bfr[ni>>1][(ni&1)*2], bfr[ni>>1][(ni&1)*2 + 1]);
        }
        __syncthreads();
    }

    // last iter: h1 tile
    #pragma unroll
    for (int i = 0; i < 2; i++) {
        int ch = t + i*256, row = ch >> 2, q = ch & 3;
        *(uint4*)(s_a + row*SA_STRIDE + q*8) = rh[i];
    }
    #pragma unroll
    for (int i = 0; i < 2; i++) {
        int ch = t + i*256;
        if (ch < 384) {
            int kr = ch / 12, q = ch % 12;
            *(uint4*)(s_b + kr*SB_STRIDE + q*8) = rb[i];
        }
    }
    __syncthreads();
    #pragma unroll
    for (int k16 = 0; k16 < 2; k16++) {
        const int kk = k16 * 16;
        uint32_t afr[2][4], bfr[3][4];
        #pragma unroll
        for (int mi = 0; mi < 2; mi++)
            ldsm4(afr[mi], sa_base + ((wm + mi*16 + a_row)*SA_STRIDE + kk + a_hi*8)*2);
        #pragma unroll
        for (int nb = 0; nb < 3; nb++)
            ldsm4t(bfr[nb], sb_base + ((kk + b_k)*SB_STRIDE + wn + nb*16 + b_hi*8)*2);
        #pragma unroll
        for (int mi = 0; mi < 2; mi++)
            #pragma unroll
            for (int ni = 0; ni < 6; ni++)
                mma16816(acc[mi][ni], afr[mi],
                         bfr[ni>>1][(ni&1)*2], bfr[ni>>1][(ni&1)*2 + 1]);
    }

    #pragma unroll
    for (int mi = 0; mi < 2; mi++) {
        const int rb_ = m0 + wm + mi*16 + (lane >> 2);
        #pragma unroll
        for (int ni = 0; ni < 6; ni++) {
            const int gc = n0 + wn + ni*8 + (lane & 3)*2;
            float* a4 = acc[mi][ni];
            if (gc < 256) {
                *(__nv_bfloat162*)(g_v + (size_t)rb_*256 + gc)
                    = __floats2bfloat162_rn(a4[0], a4[1]);
                *(__nv_bfloat162*)(g_v + (size_t)(rb_+8)*256 + gc)
                    = __floats2bfloat162_rn(a4[2], a4[3]);
            } else {
                int jc = gc - 256;
                g_s1p[(size_t)rb_*32 + jc]         = a4[0];
                g_s1p[(size_t)rb_*32 + jc + 1]     = a4[1];
                g_s1p[(size_t)(rb_+8)*32 + jc]     = a4[2];
                g_s1p[(size_t)(rb_+8)*32 + jc + 1] = a4[3];
            }
        }
    }
}

// ---------------- kAttn: single-pass fused softmax + reduce (4-wide ILP) ----------------
__global__ __launch_bounds__(256) void kAttn(
    const float* __restrict__ query, const int* __restrict__ vis,
    const float* __restrict__ ln1_g, const float* __restrict__ ln1_b,
    const float* __restrict__ sc_w2, const float* __restrict__ sc_b2,
    const float* __restrict__ pos_b2)
{
    __shared__ float s_s1d[128*64];
    __shared__ float s_xln[256];
    __shared__ float s_qs[32];
    __shared__ int   s_vis[128];
    __shared__ float s_red[8];
    __shared__ float s_part[4][128];

    const int bh = blockIdx.x, tid = threadIdx.x;
    const int lane = tid & 31, wid = tid >> 5;

    float qv = query[bh*256 + tid];
    float m = brsum(qv, s_red) * (1.f/256.f);
    float dvv = qv - m;
    float var = brsum(dvv*dvv, s_red) * (1.f/256.f);
    s_xln[tid] = dvv * rsqrtf(var + 1e-6f) * ln1_g[tid] + ln1_b[tid];
    if (tid < 128) s_vis[tid] = vis[bh*128 + tid];
    __syncthreads();

    if (wid == 0) {
        float a = 0.f;
        #pragma unroll 4
        for (int c = 0; c < 256; c++) a += s_xln[c] * g_Wqs[c*32 + lane];
        s_qs[lane] = a;
    }
    __syncthreads();

    {
        const float4* sp = (const float4*)(g_s1p + (size_t)bh * 4096);
        #pragma unroll
        for (int i = 0; i < 4; i++) {
            int i4 = tid + i*256;
            int n = i4 >> 3, jb = (i4 & 7) * 4;
            float4 v4 = sp[i4];
            float a0 = fmaxf(v4.x + g_cb[jb+0] - s_qs[jb+0], 0.f);
            float a1 = fmaxf(v4.y + g_cb[jb+1] - s_qs[jb+1], 0.f);
            float a2 = fmaxf(v4.z + g_cb[jb+2] - s_qs[jb+2], 0.f);
            float a3 = fmaxf(v4.w + g_cb[jb+3] - s_qs[jb+3], 0.f);
            float4* dd = (float4*)(s_s1d + n*64 + jb*2);
            dd[0] = make_float4(a0, a0, a1, a1);
            dd[1] = make_float4(a2, a2, a3, a3);
        }
    }
    __syncthreads();

    const int p = tid & 127, half = tid >> 7;
    const int c0 = p * 2;
    ULL w2[32];
    #pragma unroll
    for (int j = 0; j < 32; j++) w2[j] = *(const ULL*)(sc_w2 + j*256 + c0);
    const ULL sb2 = *(const ULL*)(sc_b2 + c0);

    float sum0 = 0.f, sum1 = 0.f, agg0 = 0.f, agg1 = 0.f;
    const __nv_bfloat162* vbase = (const __nv_bfloat162*)(g_v + (size_t)bh*32768) + p;
    const int nb = half * 64;
    #pragma unroll 4
    for (int n = nb; n < nb + 64; n++) {
        const ulonglong2* s1r = (const ulonglong2*)(s_s1d + n*64);
        ULL a0 = sb2, a1 = 0, a2 = 0, a3 = 0;
        #pragma unroll
        for (int j2 = 0; j2 < 8; j2++) {
            ulonglong2 sA = s1r[j2*2], sB = s1r[j2*2 + 1];
            ffma2(a0, sA.x, w2[j2*4 + 0]);
            ffma2(a1, sA.y, w2[j2*4 + 1]);
            ffma2(a2, sB.x, w2[j2*4 + 2]);
            ffma2(a3, sB.y, w2[j2*4 + 3]);
        }
        fadd2(a0, a1); fadd2(a2, a3); fadd2(a0, a2);
        float l0, l1; upk2(a0, l0, l1);
        if (s_vis[n] == 0) { l0 = -30.f; l1 = -30.f; }
        float e0 = __expf(l0), e1 = __expf(l1);
        float2 vf = __bfloat1622float2(vbase[n*128]);
        sum0 += e0; sum1 += e1;
        agg0 += e0 * vf.x; agg1 += e1 * vf.y;
    }
    if (half) {
        s_part[0][p] = sum0; s_part[1][p] = sum1;
        s_part[2][p] = agg0; s_part[3][p] = agg1;
    }
    __syncthreads();
    if (!half) {
        sum0 += s_part[0][p]; sum1 += s_part[1][p];
        agg0 += s_part[2][p]; agg1 += s_part[3][p];
        float2 o;
        o.x = agg0 / sum0 + pos_b2[c0];
        o.y = agg1 / sum1 + pos_b2[c0 + 1];
        *(float2*)(g_agg + bh*256 + c0) = o;
    }
}

// ---------------- kOut: agg@Wo + bo + residual, LN2 -> split bf16 ----------------
__global__ __launch_bounds__(256) void kOut(
    const float* __restrict__ query, const float* __restrict__ Wo,
    const float* __restrict__ bo,
    const float* __restrict__ ln2_g, const float* __restrict__ ln2_b)
{
    __shared__ float s_a[256];
    __shared__ float s_red[8];
    const int bh = blockIdx.x, c = threadIdx.x;
    s_a[c] = g_agg[bh*256 + c];
    __syncthreads();
    float acc = bo[c];
    #pragma unroll 4
    for (int d = 0; d < 256; d += 4) {
        float4 a4 = *(const float4*)(s_a + d);
        acc += a4.x*Wo[(d+0)*256 + c];
        acc += a4.y*Wo[(d+1)*256 + c];
        acc += a4.z*Wo[(d+2)*256 + c];
        acc += a4.w*Wo[(d+3)*256 + c];
    }
    float x2 = acc + query[bh*256 + c];
    g_x[bh*256 + c] = x2;
    float m = brsum(x2, s_red) * (1.f/256.f);
    float dv = x2 - m;
    float var = brsum(dv*dv, s_red) * (1.f/256.f);
    float rstd = rsqrtf(var + 1e-6f);
    float xlnv = dv * rstd * ln2_g[c] + ln2_b[c];
    __nv_bfloat16 h, l; bsplit(xlnv, h, l);
    g_xlns[(size_t)bh*768 + c]       = h;
    g_xlns[(size_t)bh*768 + 256 + c] = l;
    g_xlns[(size_t)bh*768 + 512 + c] = h;
}

// ---------------- kFF1m: h = relu(xln @ w1 + b1), split-bf16, K'=768 ----------------
#define FB_STRIDE 136

__global__ __launch_bounds__(256) void kFF1m(const float* __restrict__ ff_b1) {
    __shared__ __align__(16) __nv_bfloat16 s_a[128 * SA_STRIDE];
    __shared__ __align__(16) __nv_bfloat16 s_b[32 * FB_STRIDE];

    const int t = threadIdx.x, lane = t & 31, wid = t >> 5;
    const int wm = (wid & 3) * 32, wn = (wid >> 2) * 64;
    const int n0 = blockIdx.x * 128, m0 = blockIdx.y * 128;

    float acc[2][8][4];
    #pragma unroll
    for (int i = 0; i < 2; i++)
        #pragma unroll
        for (int j = 0; j < 8; j++)
            #pragma unroll
            for (int k = 0; k < 4; k++) acc[i][j][k] = 0.f;

    const uint32_t sa_base = (uint32_t)__cvta_generic_to_shared(s_a);
    const uint32_t sb_base = (uint32_t)__cvta_generic_to_shared(s_b);
    const int a_row = lane & 15, a_hi = lane >> 4;
    const int b_k   = lane & 15, b_hi = lane >> 4;

    uint4 ra[2], rbv[2];
    #pragma unroll
    for (int i = 0; i < 2; i++) {
        int ch = t + i*256, row = ch >> 2, q = ch & 3;
        ra[i] = *(const uint4*)(g_xlns + (size_t)(m0+row)*768 + q*8);
    }
    #pragma unroll
    for (int i = 0; i < 2; i++) {
        int ch = t + i*256, kr = ch >> 4, q = ch & 15;
        rbv[i] = *(const uint4*)(g_w1s + (size_t)kr*1024 + n0 + q*8);
    }

    for (int it = 0; it < 24; it++) {
        #pragma unroll
        for (int i = 0; i < 2; i++) {
            int ch = t + i*256, row = ch >> 2, q = ch & 3;
            *(uint4*)(s_a + row*SA_STRIDE + q*8) = ra[i];
        }
        #pragma unroll
        for (int i = 0; i < 2; i++) {
            int ch = t + i*256, kr = ch >> 4, q = ch & 15;
            *(uint4*)(s_b + kr*FB_STRIDE + q*8) = rbv[i];
        }
        __syncthreads();
        if (it < 23) {
            const int kb = (it+1) * 32;
            #pragma unroll
            for (int i = 0; i < 2; i++) {
                int ch = t + i*256, row = ch >> 2, q = ch & 3;
                ra[i] = *(const uint4*)(g_xlns + (size_t)(m0+row)*768 + kb + q*8);
            }
            #pragma unroll
            for (int i = 0; i < 2; i++) {
                int ch = t + i*256, kr = ch >> 4, q = ch & 15;
                rbv[i] = *(const uint4*)(g_w1s + (size_t)(kb+kr)*1024 + n0 + q*8);
            }
        }
        #pragma unroll
        for (int k16 = 0; k16 < 2; k16++) {
            const int kk = k16 * 16;
            uint32_t afr[2][4], bfr[4][4];
            #pragma unroll
            for (int mi = 0; mi < 2; mi++)
                ldsm4(afr[mi], sa_base + ((wm + mi*16 + a_row)*SA_STRIDE + kk + a_hi*8)*2);
            #pragma unroll
            for (int nbk = 0; nbk < 4; nbk++)
                ldsm4t(bfr[nbk], sb_base + ((kk + b_k)*FB_STRIDE + wn + nbk*16 + b_hi*8)*2);
            #pragma unroll
            for (int mi = 0; mi < 2; mi++)
                #pragma unroll
                for (int ni = 0; ni < 8; ni++)
                    mma16816(acc[mi][ni], afr[mi],
                             bfr[ni>>1][(ni&1)*2], bfr[ni>>1][(ni&1)*2 + 1]);
        }
        __syncthreads();
    }

    #pragma unroll
    for (int mi = 0; mi < 2; mi++) {
        const int rb_ = m0 + wm + mi*16 + (lane >> 2);
        #pragma unroll
        for (int ni = 0; ni < 8; ni++) {
            const int gc = n0 + wn + ni*8 + (lane & 3)*2;
            float b0 = ff_b1[gc], b1 = ff_b1[gc + 1];
            float* a4 = acc[mi][ni];
            float h0 = fmaxf(a4[0] + b0, 0.f), h1v = fmaxf(a4[1] + b1, 0.f);
            float h2 = fmaxf(a4[2] + b0, 0.f), h3v = fmaxf(a4[3] + b1, 0.f);
            __nv_bfloat16 hh0, ll0, hh1, ll1, hh2, ll2, hh3, ll3;
            bsplit(h0, hh0, ll0); bsplit(h1v, hh1, ll1);
            bsplit(h2, hh2, ll2); bsplit(h3v, hh3, ll3);
            __nv_bfloat16* r0 = g_hbs + (size_t)rb_*3072;
            __nv_bfloat16* r1 = g_hbs + (size_t)(rb_+8)*3072;
            *(__nv_bfloat162*)(r0 + gc)        = __nv_bfloat162(hh0, hh1);
            *(__nv_bfloat162*)(r0 + 1024 + gc) = __nv_bfloat162(ll0, ll1);
            *(__nv_bfloat162*)(r0 + 2048 + gc) = __nv_bfloat162(hh0, hh1);
            *(__nv_bfloat162*)(r1 + gc)        = __nv_bfloat162(hh2, hh3);
            *(__nv_bfloat162*)(r1 + 1024 + gc) = __nv_bfloat162(ll2, ll3);
            *(__nv_bfloat162*)(r1 + 2048 + gc) = __nv_bfloat162(hh2, hh3);
        }
    }
}

// ---------------- kFF2m: out = h @ w2 + b2 + x, split-bf16, K'=3072 ----------------
__global__ __launch_bounds__(256) void kFF2m(
    const float* __restrict__ ff_b2, float* __restrict__ out)
{
    __shared__ __align__(16) __nv_bfloat16 s_a[64 * SA_STRIDE];
    __shared__ __align__(16) __nv_bfloat16 s_b[32 * FB_STRIDE];

    const int t = threadIdx.x, lane = t & 31, wid = t >> 5;
    const int wm = (wid & 1) * 32, wn = (wid >> 1) * 32;
    const int n0 = blockIdx.x * 128, m0 = blockIdx.y * 64;

    float acc[2][4][4];
    #pragma unroll
    for (int i = 0; i < 2; i++)
        #pragma unroll
        for (int j = 0; j < 4; j++)
            #pragma unroll
            for (int k = 0; k < 4; k++) acc[i][j][k] = 0.f;

    const uint32_t sa_base = (uint32_t)__cvta_generic_to_shared(s_a);
    const uint32_t sb_base = (uint32_t)__cvta_generic_to_shared(s_b);
    const int a_row = lane & 15, a_hi = lane >> 4;
    const int b_k   = lane & 15, b_hi = lane >> 4;

    uint4 ra, rbv[2];
    {
        int row = t >> 2, q = t & 3;
        ra = *(const uint4*)(g_hbs + (size_t)(m0+row)*3072 + q*8);
    }
    #pragma unroll
    for (int i = 0; i < 2; i++) {
        int ch = t + i*256, kr = ch >> 4, q = ch & 15;
        rbv[i] = *(const uint4*)(g_w2s + (size_t)kr*256 + n0 + q*8);
    }

    for (int it = 0; it < 96; it++) {
        {
            int row = t >> 2, q = t & 3;
            *(uint4*)(s_a + row*SA_STRIDE + q*8) = ra;
        }
        #pragma unroll
        for (int i = 0; i < 2; i++) {
            int ch = t + i*256, kr = ch >> 4, q = ch & 15;
            *(uint4*)(s_b + kr*FB_STRIDE + q*8) = rbv[i];
        }
        __syncthreads();
        if (it < 95) {
            const int kb = (it+1) * 32;
            int row = t >> 2, q = t & 3;
            ra = *(const uint4*)(g_hbs + (size_t)(m0+row)*3072 + kb + q*8);
            #pragma unroll
            for (int i = 0; i < 2; i++) {
                int ch = t + i*256, kr = ch >> 4, q2 = ch & 15;
                rbv[i] = *(const uint4*)(g_w2s + (size_t)(kb+kr)*256 + n0 + q2*8);
            }
        }
        #pragma unroll
        for (int k16 = 0; k16 < 2; k16++) {
            const int kk = k16 * 16;
            uint32_t afr[2][4], bfr[2][4];
            #pragma unroll
            for (int mi = 0; mi < 2; mi++)
                ldsm4(afr[mi], sa_base + ((wm + mi*16 + a_row)*SA_STRIDE + kk + a_hi*8)*2);
            #pragma unroll
            for (int nbk = 0; nbk < 2; nbk++)
                ldsm4t(bfr[nbk], sb_base + ((kk + b_k)*FB_STRIDE + wn + nbk*16 + b_hi*8)*2);
            #pragma unroll
            for (int mi = 0; mi < 2; mi++)
                #pragma unroll
                for (int ni = 0; ni < 4; ni++)
                    mma16816(acc[mi][ni], afr[mi],
                             bfr[ni>>1][(ni&1)*2], bfr[ni>>1][(ni&1)*2 + 1]);
        }
        __syncthreads();
    }

    #pragma unroll
    for (int mi = 0; mi < 2; mi++) {
        const int rb_ = m0 + wm + mi*16 + (lane >> 2);
        #pragma unroll
        for (int ni = 0; ni < 4; ni++) {
            const int gc = n0 + wn + ni*8 + (lane & 3)*2;
            float b0 = ff_b2[gc], b1 = ff_b2[gc + 1];
            float* a4 = acc[mi][ni];
            float2 x0 = *(const float2*)(g_x + (size_t)rb_*256 + gc);
            float2 x1 = *(const float2*)(g_x + (size_t)(rb_+8)*256 + gc);
            *(float2*)(out + (size_t)rb_*256 + gc)
                = make_float2(a4[0] + b0 + x0.x, a4[1] + b1 + x0.y);
            *(float2*)(out + (size_t)(rb_+8)*256 + gc)
                = make_float2(a4[2] + b0 + x1.x, a4[3] + b1 + x1.y);
        }
    }
}

// ---------------- launch ----------------
extern "C" void kernel_launch(void* const* d_in, const int* in_sizes, int n_in,
                              void* d_out, int out_size) {
    (void)in_sizes; (void)n_in; (void)out_size;
    const float* query  = (const float*)d_in[0];
    const float* key    = (const float*)d_in[1];
    const float* rel    = (const float*)d_in[2];
    const int*   vis    = (const int*)  d_in[3];
    const float* ln1_g  = (const float*)d_in[4];
    const float* ln1_b  = (const float*)d_in[5];
    const float* ln2_g  = (const float*)d_in[6];
    const float* ln2_b  = (const float*)d_in[7];
    const float* Wq     = (const float*)d_in[8];
    const float* Wk     = (const float*)d_in[9];
    const float* Wv     = (const float*)d_in[10];
    const float* pos_w1 = (const float*)d_in[11];
    const float* pos_b1 = (const float*)d_in[12];
    const float* pos_w2 = (const float*)d_in[13];
    const float* pos_b2 = (const float*)d_in[14];
    const float* sc_w1  = (const float*)d_in[15];
    const float* sc_b1  = (const float*)d_in[16];
    const float* sc_w2  = (const float*)d_in[17];
    const float* sc_b2  = (const float*)d_in[18];
    const float* Wo     = (const float*)d_in[19];
    const float* bo     = (const float*)d_in[20];
    const float* ff_w1  = (const float*)d_in[21];
    const float* ff_b1  = (const float*)d_in[22];
    const float* ff_w2  = (const float*)d_in[23];
    const float* ff_b2  = (const float*)d_in[24];
    float* out = (float*)d_out;

    kFold<<<65, 256>>>(Wq, Wk, sc_w1, sc_b1, pos_w2, pos_b2);
    kPrep<<<BHTOK + 1 + 768, 256>>>(rel, pos_w1, pos_b1, Wv, pos_w2, ff_w1, ff_w2);
    kGemm<<<dim3(3, 1024), 256>>>(key);
    kAttn<<<BHTOK, 256>>>(query, vis, ln1_g, ln1_b, sc_w2, sc_b2, pos_b2);
    kOut<<<BHTOK, 256>>>(query, Wo, bo, ln2_g, ln2_b);
    kFF1m<<<dim3(8, 8), 256>>>(ff_b1);
    kFF2m<<<dim3(2, 16), 256>>>(ff_b2, out);
}